// round 10
// baseline (speedup 1.0000x reference)
#include <cuda_runtime.h>
#include <cuda_fp16.h>
#include <cstdint>

#define T_TOKENS 8192
#define DIM      1024
#define HID      4096
#define H2       8192
#define NE       8
#define PAIRS    16384
#define TM       128
#define KC       64              // K halves per chunk (128B row)
#define ROWB     144             // padded row stride (conflict-free ldmatrix)
#define MAXTILES 136
#define NK1      (DIM/KC)        // 16
#define NK2      (HID/KC)        // 64
#define NSTG     4               // cp.async pipeline stages

// dynamic smem layout (per CTA) — 4-stage, 1 CTA/SM
#define OFF_SP   0
#define OFF_BIAS 512
#define OFF_A    2048
#define ABUF     (128*ROWB)      // 18432 per stage
#define OFF_B    (OFF_A + NSTG*ABUF)
#define SMEM_TOTAL (OFF_B + NSTG*ABUF)   // 149504

// ---------------- device scratch ----------------
__device__ float  g_gate[PAIRS];
__device__ int    g_pairlist[NE * PAIRS];
__device__ int    g_count[NE];
__device__ __half g_xb[T_TOKENS * DIM];
__device__ __half g_w1b[(size_t)NE * H2 * DIM];
__device__ __half g_w2b[(size_t)NE * DIM * HID];
__device__ __half g_hbuf[(size_t)PAIRS * HID];

// ---------------- helpers ----------------
__device__ __forceinline__ uint32_t smem_u32(const void* p) {
    return (uint32_t)__cvta_generic_to_shared(p);
}
__device__ __forceinline__ void cp16(uint32_t dst, const void* src, int sz) {
    asm volatile("cp.async.cg.shared.global [%0], [%1], 16, %2;\n" :: "r"(dst), "l"(src), "r"(sz));
}
#define CP_COMMIT() asm volatile("cp.async.commit_group;\n")
#define CP_WAIT2()  asm volatile("cp.async.wait_group 2;\n")
#define CP_WAIT1()  asm volatile("cp.async.wait_group 1;\n")
#define CP_WAIT0()  asm volatile("cp.async.wait_group 0;\n")

#define LDSM4(r, addr) \
    asm volatile("ldmatrix.sync.aligned.m8n8.x4.shared.b16 {%0,%1,%2,%3}, [%4];" \
        : "=r"((r)[0]), "=r"((r)[1]), "=r"((r)[2]), "=r"((r)[3]) : "r"(addr))

__device__ __forceinline__ void mma_f16(float c[4], const uint32_t a[4],
                                        uint32_t b0, uint32_t b1) {
    asm volatile(
        "mma.sync.aligned.m16n8k16.row.col.f32.f16.f16.f32 "
        "{%0,%1,%2,%3}, {%4,%5,%6,%7}, {%8,%9}, {%0,%1,%2,%3};\n"
        : "+f"(c[0]), "+f"(c[1]), "+f"(c[2]), "+f"(c[3])
        : "r"(a[0]), "r"(a[1]), "r"(a[2]), "r"(a[3]), "r"(b0), "r"(b1));
}

// map tile index -> (expert, m0); returns expert or -1
__device__ __forceinline__ int tile_map(int bx, int& m0, int& cnt) {
    int off = 0, e = -1;
#pragma unroll
    for (int i = 0; i < NE; i++) {
        int c = g_count[i];
        int t = (c + TM - 1) / TM;
        if (e < 0 && bx < off + t) { e = i; m0 = (bx - off) * TM; cnt = c; }
        off += t;
    }
    return e;
}

// ---------------- fused prep: counter clear + out zero + all fp32->fp16 converts ----------------
__device__ __forceinline__ void f2h_body(const float4* __restrict__ src,
                                         float2* __restrict__ dst, int n4) {
    int stride = gridDim.x * blockDim.x;
    for (int i = blockIdx.x * blockDim.x + threadIdx.x; i < n4; i += stride) {
        float4 v = src[i];
        union { __half2 h2[2]; float2 f; } u;
        u.h2[0] = __float22half2_rn(make_float2(v.x, v.y));
        u.h2[1] = __float22half2_rn(make_float2(v.z, v.w));
        dst[i] = u.f;
    }
}
__global__ void prep_kernel(const float* __restrict__ x,
                            const float* __restrict__ w1,
                            const float* __restrict__ w2,
                            float* __restrict__ out, int out4) {
    if (blockIdx.x == 0 && threadIdx.x < NE) g_count[threadIdx.x] = 0;
    int stride = gridDim.x * blockDim.x;
    float4 z = make_float4(0.f, 0.f, 0.f, 0.f);
    float4* o4 = (float4*)out;
    for (int i = blockIdx.x * blockDim.x + threadIdx.x; i < out4; i += stride) o4[i] = z;
    f2h_body((const float4*)x,  (float2*)g_xb,  T_TOKENS * DIM / 4);
    f2h_body((const float4*)w1, (float2*)g_w1b, (int)((size_t)NE * H2 * DIM / 4));
    f2h_body((const float4*)w2, (float2*)g_w2b, (int)((size_t)NE * DIM * HID / 4));
}

__global__ void router_kernel(const float* __restrict__ x,
                              const float* __restrict__ rw,
                              const float* __restrict__ rb) {
    __shared__ float srw[NE * DIM];
    int tid = threadIdx.x;
    for (int i = tid; i < NE * DIM; i += 256) srw[i] = rw[i];
    __syncthreads();
    int warp = tid >> 5, lane = tid & 31;
    int t = blockIdx.x * 8 + warp;
    float xr[32];
#pragma unroll
    for (int i = 0; i < 32; i++) xr[i] = x[(size_t)t * DIM + i * 32 + lane];
    float lg[NE];
#pragma unroll
    for (int e = 0; e < NE; e++) {
        float s = 0.f;
#pragma unroll
        for (int i = 0; i < 32; i++) s += xr[i] * srw[e * DIM + i * 32 + lane];
#pragma unroll
        for (int o = 16; o > 0; o >>= 1) s += __shfl_xor_sync(0xffffffffu, s, o);
        lg[e] = s + rb[e];
    }
    if (lane == 0) {
        int i0 = 0;
#pragma unroll
        for (int e = 1; e < NE; e++) if (lg[e] > lg[i0]) i0 = e;
        int i1 = (i0 == 0) ? 1 : 0;
#pragma unroll
        for (int e = 0; e < NE; e++) {
            if (e == i0) continue;
            if (lg[e] > lg[i1]) i1 = e;
        }
        float e1 = __expf(lg[i1] - lg[i0]);
        g_gate[2 * t]     = 1.f / (1.f + e1);
        g_gate[2 * t + 1] = e1 / (1.f + e1);
        int pos0 = atomicAdd(&g_count[i0], 1);
        g_pairlist[i0 * PAIRS + pos0] = 2 * t;
        int pos1 = atomicAdd(&g_count[i1], 1);
        g_pairlist[i1 * PAIRS + pos1] = 2 * t + 1;
    }
}

// 4-stage mainloop + explicit fragment double-buffering (1 CTA/SM, high regs).
// Fill(kt+3) writes the stage computed at kt-1 (ordered by this iteration's
// barrier). Tail drain: wait_group 2 / 1 / 0 so fill(kt) is always complete.
#define GEMM_MAINLOOP(NKC)                                                          \
    FILL(0, 0); FILL(1, 1); FILL(2, 2);                                             \
    for (int kt = 0; kt < (NKC); kt++) {                                            \
        int buf = kt & 3;                                                           \
        if (kt < (NKC) - 2)       CP_WAIT2();                                       \
        else if (kt == (NKC) - 2) CP_WAIT1();                                       \
        else                      CP_WAIT0();                                       \
        __syncthreads();                                                            \
        if (kt + 3 < (NKC)) FILL((kt + 3) & 3, kt + 3);                             \
        uint32_t ab = aBase + buf * ABUF, bb = bBase + buf * ABUF;                  \
        uint32_t fa[2][2][4], fb[2][4][4];                                          \
        LDSM4(fa[0][0], ab);                                                        \
        LDSM4(fa[0][1], ab + 16 * ROWB);                                            \
        LDSM4(fb[0][0], bb);                                                        \
        LDSM4(fb[0][1], bb + 16 * ROWB);                                            \
        LDSM4(fb[0][2], bb + 32 * ROWB);                                            \
        LDSM4(fb[0][3], bb + 48 * ROWB);                                            \
        _Pragma("unroll")                                                           \
        for (int ks = 0; ks < 4; ks++) {                                            \
            int cur = ks & 1, nxt = cur ^ 1;                                        \
            if (ks < 3) {                                                           \
                LDSM4(fa[nxt][0], ab + (ks + 1) * 32);                              \
                LDSM4(fa[nxt][1], ab + 16 * ROWB + (ks + 1) * 32);                  \
                _Pragma("unroll")                                                   \
                for (int j = 0; j < 4; j++)                                         \
                    LDSM4(fb[nxt][j], bb + j * 16 * ROWB + (ks + 1) * 32);          \
            }                                                                       \
            _Pragma("unroll")                                                       \
            for (int f = 0; f < 8; f++) {                                           \
                int j = f >> 1, h = f & 1;                                          \
                mma_f16(acc[0][f], fa[cur][0], fb[cur][j][h], fb[cur][j][h + 2]);   \
                mma_f16(acc[1][f], fa[cur][1], fb[cur][j][h], fb[cur][j][h + 2]);   \
            }                                                                       \
        }                                                                           \
    }

// ---------------- GEMM1: h = swiglu(x @ w1^T + b1) ----------------
__global__ void __launch_bounds__(256, 1) gemm1_kernel(const float* __restrict__ b1) {
    extern __shared__ __align__(1024) char sm[];
    uint32_t sb = smem_u32(sm);
    int tid = threadIdx.x;
    int m0 = 0, cnt = 0;
    int e = tile_map(blockIdx.x, m0, cnt);
    if (e < 0) return;
    int rows = min(TM, cnt - m0);
    int n0   = blockIdx.y * 64;

    int*   sp    = (int*)(sm + OFF_SP);
    float* sbias = (float*)(sm + OFF_BIAS);
    if (tid < TM) sp[tid] = (tid < rows) ? g_pairlist[e * PAIRS + m0 + tid] : -1;
    if (tid < 64) {
        sbias[tid]      = b1[(size_t)e * H2 + n0 + tid];
        sbias[64 + tid] = b1[(size_t)e * H2 + HID + n0 + tid];
    }
    __syncthreads();

    int kk = tid & 7, fr = tid >> 3;
    const __half* asrc[4]; int asz[4];
#pragma unroll
    for (int i = 0; i < 4; i++) {
        int p = sp[fr + 32 * i];
        asrc[i] = g_xb + (size_t)((p >= 0) ? (p >> 1) : 0) * DIM + kk * 8;
        asz[i]  = (p >= 0) ? 16 : 0;
    }
    const __half* wb = g_w1b + (size_t)e * H2 * DIM;
    const __half* bsrc[4];
#pragma unroll
    for (int i = 0; i < 4; i++) {
        int grow = n0 + (i >> 1) * 32 + fr + (i & 1) * HID;
        bsrc[i] = wb + (size_t)grow * DIM + kk * 8;
    }
    uint32_t adst = sb + OFF_A + fr * ROWB + kk * 16;
    uint32_t bdst = sb + OFF_B + fr * ROWB + kk * 16;

#define FILL(bufi, ktv) do {                                                   \
    uint32_t ao = (bufi) * (uint32_t)ABUF; int ks = (ktv) * KC;                \
    _Pragma("unroll") for (int i = 0; i < 4; i++)                              \
        cp16(adst + ao + i * 32 * ROWB, asrc[i] + ks, asz[i]);                 \
    _Pragma("unroll") for (int i = 0; i < 4; i++)                              \
        cp16(bdst + ao + i * 32 * ROWB, bsrc[i] + ks, 16);                     \
    CP_COMMIT(); } while (0)

    float acc[2][8][4];
#pragma unroll
    for (int mi = 0; mi < 2; mi++)
#pragma unroll
        for (int f = 0; f < 8; f++)
#pragma unroll
            for (int q = 0; q < 4; q++) acc[mi][f][q] = 0.f;

    int warp = tid >> 5, lane = tid & 31;
    int wm = warp >> 1, wn = warp & 1;
    uint32_t lrow = lane & 15, lko = (lane >> 4) * 16;
    uint32_t aBase = sb + OFF_A + (wm * 32 + lrow) * ROWB + lko;
    uint32_t bBase = sb + OFF_B + (wn * 64 + lrow) * ROWB + lko;

    GEMM_MAINLOOP(NK1)
#undef FILL

    int g = lane >> 2, tg = lane & 3;
#pragma unroll
    for (int mi = 0; mi < 2; mi++) {
        int rb = wm * 32 + mi * 16 + g;
#pragma unroll
        for (int f = 0; f < 4; f++) {
            int jj = wn * 32 + f * 8 + 2 * tg;
            float bg0 = sbias[jj],      bg1 = sbias[jj + 1];
            float bu0 = sbias[64 + jj], bu1 = sbias[64 + jj + 1];
            int j = n0 + jj;
            if (rb < rows) {
                int p = sp[rb];
                float ga = acc[mi][f][0] + bg0, ua = acc[mi][f + 4][0] + bu0;
                float gb = acc[mi][f][1] + bg1, ub = acc[mi][f + 4][1] + bu1;
                float h0 = ga / (1.f + __expf(-ga)) * ua;
                float h1 = gb / (1.f + __expf(-gb)) * ub;
                *(__half2*)&g_hbuf[(size_t)p * HID + j] = __floats2half2_rn(h0, h1);
            }
            if (rb + 8 < rows) {
                int p = sp[rb + 8];
                float ga = acc[mi][f][2] + bg0, ua = acc[mi][f + 4][2] + bu0;
                float gb = acc[mi][f][3] + bg1, ub = acc[mi][f + 4][3] + bu1;
                float h0 = ga / (1.f + __expf(-ga)) * ua;
                float h1 = gb / (1.f + __expf(-gb)) * ub;
                *(__half2*)&g_hbuf[(size_t)p * HID + j] = __floats2half2_rn(h0, h1);
            }
        }
    }
}

// ---------------- GEMM2: out += gate * (h @ w2^T + b2)  (m-fastest grid, R8-proven) ----------------
__global__ void __launch_bounds__(256, 1) gemm2_kernel(const float* __restrict__ b2,
                                                       float* __restrict__ out) {
    extern __shared__ __align__(1024) char sm[];
    uint32_t sb = smem_u32(sm);
    int tid = threadIdx.x;
    int m0 = 0, cnt = 0;
    int e = tile_map(blockIdx.x, m0, cnt);
    if (e < 0) return;
    int rows = min(TM, cnt - m0);
    int n0   = blockIdx.y * 128;

    int*   sp    = (int*)(sm + OFF_SP);
    float* sbias = (float*)(sm + OFF_BIAS);
    if (tid < TM) sp[tid] = (tid < rows) ? g_pairlist[e * PAIRS + m0 + tid] : -1;
    if (tid < 128) sbias[tid] = b2[(size_t)e * DIM + n0 + tid];
    __syncthreads();

    int kk = tid & 7, fr = tid >> 3;
    const __half* asrc[4]; int asz[4];
#pragma unroll
    for (int i = 0; i < 4; i++) {
        int p = sp[fr + 32 * i];
        asrc[i] = g_hbuf + (size_t)((p >= 0) ? p : 0) * HID + kk * 8;
        asz[i]  = (p >= 0) ? 16 : 0;
    }
    const __half* wb = g_w2b + (size_t)e * DIM * HID;
    const __half* bsrc[4];
#pragma unroll
    for (int i = 0; i < 4; i++) bsrc[i] = wb + (size_t)(n0 + fr + 32 * i) * HID + kk * 8;
    uint32_t adst = sb + OFF_A + fr * ROWB + kk * 16;
    uint32_t bdst = sb + OFF_B + fr * ROWB + kk * 16;

#define FILL(bufi, ktv) do {                                                   \
    uint32_t ao = (bufi) * (uint32_t)ABUF; int ks = (ktv) * KC;                \
    _Pragma("unroll") for (int i = 0; i < 4; i++)                              \
        cp16(adst + ao + i * 32 * ROWB, asrc[i] + ks, asz[i]);                 \
    _Pragma("unroll") for (int i = 0; i < 4; i++)                              \
        cp16(bdst + ao + i * 32 * ROWB, bsrc[i] + ks, 16);                     \
    CP_COMMIT(); } while (0)

    float acc[2][8][4];
#pragma unroll
    for (int mi = 0; mi < 2; mi++)
#pragma unroll
        for (int f = 0; f < 8; f++)
#pragma unroll
            for (int q = 0; q < 4; q++) acc[mi][f][q] = 0.f;

    int warp = tid >> 5, lane = tid & 31;
    int wm = warp >> 1, wn = warp & 1;
    uint32_t lrow = lane & 15, lko = (lane >> 4) * 16;
    uint32_t aBase = sb + OFF_A + (wm * 32 + lrow) * ROWB + lko;
    uint32_t bBase = sb + OFF_B + (wn * 64 + lrow) * ROWB + lko;

    GEMM_MAINLOOP(NK2)
#undef FILL

    int g = lane >> 2, tg = lane & 3;
#pragma unroll
    for (int mi = 0; mi < 2; mi++) {
        int rb = wm * 32 + mi * 16 + g;
#pragma unroll
        for (int f = 0; f < 8; f++) {
            int jj = wn * 64 + f * 8 + 2 * tg;
            int j = n0 + jj;
            float bb0 = sbias[jj], bb1 = sbias[jj + 1];
            if (rb < rows) {
                int p = sp[rb];
                int t = p >> 1;
                float w = g_gate[p];
                atomicAdd(&out[(size_t)t * DIM + j],     (acc[mi][f][0] + bb0) * w);
                atomicAdd(&out[(size_t)t * DIM + j + 1], (acc[mi][f][1] + bb1) * w);
            }
            if (rb + 8 < rows) {
                int p = sp[rb + 8];
                int t = p >> 1;
                float w = g_gate[p];
                atomicAdd(&out[(size_t)t * DIM + j],     (acc[mi][f][2] + bb0) * w);
                atomicAdd(&out[(size_t)t * DIM + j + 1], (acc[mi][f][3] + bb1) * w);
            }
        }
    }
}

// ---------------- launch: 4 kernels; gemm2 at slot 3 (ncu capture slot) ----------------
extern "C" void kernel_launch(void* const* d_in, const int* in_sizes, int n_in,
                              void* d_out, int out_size) {
    const float* x  = (const float*)d_in[0];
    const float* rw = (const float*)d_in[1];
    const float* rb = (const float*)d_in[2];
    const float* w1 = (const float*)d_in[3];
    const float* b1 = (const float*)d_in[4];
    const float* w2 = (const float*)d_in[5];
    const float* b2 = (const float*)d_in[6];
    float* out = (float*)d_out;

    cudaFuncSetAttribute(gemm1_kernel, cudaFuncAttributeMaxDynamicSharedMemorySize, SMEM_TOTAL);
    cudaFuncSetAttribute(gemm2_kernel, cudaFuncAttributeMaxDynamicSharedMemorySize, SMEM_TOTAL);

    prep_kernel<<<2048, 256>>>(x, w1, w2, out, out_size / 4);               // idx 0
    router_kernel<<<T_TOKENS / 8, 256>>>(x, rw, rb);                        // idx 1
    gemm1_kernel<<<dim3(MAXTILES, HID / 64), 256, SMEM_TOTAL>>>(b1);        // idx 2
    gemm2_kernel<<<dim3(MAXTILES, DIM / 128), 256, SMEM_TOTAL>>>(b2, out);  // idx 3 (ncu target)
}

// round 11
// speedup vs baseline: 1.0601x; 1.0601x over previous
#include <cuda_runtime.h>
#include <cuda_fp16.h>
#include <cstdint>

#define T_TOKENS 8192
#define DIM      1024
#define HID      4096
#define H2       8192
#define NE       8
#define PAIRS    16384
#define TM       128
#define KC       64              // K halves per chunk (128B row)
#define ROWB     144             // padded row stride (conflict-free ldmatrix)
#define MAXTILES 136
#define NK1      (DIM/KC)        // 16
#define NK2      (HID/KC)        // 64

// CTA tile: 128(M) x 256(B-rows). Warp tile 64x64, warps (wm,wn) = (2,4).
// smem: A 2 x 128*144, B 2 x 256*144  (1 CTA/SM)
#define OFF_SP   0
#define OFF_BIAS 512
#define OFF_A    2048
#define ABUF_A   (128*ROWB)      // 18432
#define ABUF_B   (256*ROWB)      // 36864
#define OFF_B    (OFF_A + 2*ABUF_A)
#define SMEM_TOTAL (OFF_B + 2*ABUF_B)   // 112640

// ---------------- device scratch ----------------
__device__ float  g_gate[PAIRS];
__device__ int    g_pairlist[NE * PAIRS];
__device__ int    g_count[NE];
__device__ __half g_xb[T_TOKENS * DIM];
__device__ __half g_w1b[(size_t)NE * H2 * DIM];
__device__ __half g_w2b[(size_t)NE * DIM * HID];
__device__ __half g_hbuf[(size_t)PAIRS * HID];

// ---------------- helpers ----------------
__device__ __forceinline__ uint32_t smem_u32(const void* p) {
    return (uint32_t)__cvta_generic_to_shared(p);
}
__device__ __forceinline__ void cp16(uint32_t dst, const void* src, int sz) {
    asm volatile("cp.async.cg.shared.global [%0], [%1], 16, %2;\n" :: "r"(dst), "l"(src), "r"(sz));
}
#define CP_COMMIT() asm volatile("cp.async.commit_group;\n")
#define CP_WAIT0()  asm volatile("cp.async.wait_group 0;\n")

#define LDSM4(r, addr) \
    asm volatile("ldmatrix.sync.aligned.m8n8.x4.shared.b16 {%0,%1,%2,%3}, [%4];" \
        : "=r"((r)[0]), "=r"((r)[1]), "=r"((r)[2]), "=r"((r)[3]) : "r"(addr))

__device__ __forceinline__ void mma_f16(float c[4], const uint32_t a[4],
                                        uint32_t b0, uint32_t b1) {
    asm volatile(
        "mma.sync.aligned.m16n8k16.row.col.f32.f16.f16.f32 "
        "{%0,%1,%2,%3}, {%4,%5,%6,%7}, {%8,%9}, {%0,%1,%2,%3};\n"
        : "+f"(c[0]), "+f"(c[1]), "+f"(c[2]), "+f"(c[3])
        : "r"(a[0]), "r"(a[1]), "r"(a[2]), "r"(a[3]), "r"(b0), "r"(b1));
}

// map tile index -> (expert, m0); returns expert or -1
__device__ __forceinline__ int tile_map(int bx, int& m0, int& cnt) {
    int off = 0, e = -1;
#pragma unroll
    for (int i = 0; i < NE; i++) {
        int c = g_count[i];
        int t = (c + TM - 1) / TM;
        if (e < 0 && bx < off + t) { e = i; m0 = (bx - off) * TM; cnt = c; }
        off += t;
    }
    return e;
}

// ---------------- fused prep: counter clear + out zero + all fp32->fp16 converts ----------------
__device__ __forceinline__ void f2h_body(const float4* __restrict__ src,
                                         float2* __restrict__ dst, int n4) {
    int stride = gridDim.x * blockDim.x;
    for (int i = blockIdx.x * blockDim.x + threadIdx.x; i < n4; i += stride) {
        float4 v = src[i];
        union { __half2 h2[2]; float2 f; } u;
        u.h2[0] = __float22half2_rn(make_float2(v.x, v.y));
        u.h2[1] = __float22half2_rn(make_float2(v.z, v.w));
        dst[i] = u.f;
    }
}
__global__ void prep_kernel(const float* __restrict__ x,
                            const float* __restrict__ w1,
                            const float* __restrict__ w2,
                            float* __restrict__ out, int out4) {
    if (blockIdx.x == 0 && threadIdx.x < NE) g_count[threadIdx.x] = 0;
    int stride = gridDim.x * blockDim.x;
    float4 z = make_float4(0.f, 0.f, 0.f, 0.f);
    float4* o4 = (float4*)out;
    for (int i = blockIdx.x * blockDim.x + threadIdx.x; i < out4; i += stride) o4[i] = z;
    f2h_body((const float4*)x,  (float2*)g_xb,  T_TOKENS * DIM / 4);
    f2h_body((const float4*)w1, (float2*)g_w1b, (int)((size_t)NE * H2 * DIM / 4));
    f2h_body((const float4*)w2, (float2*)g_w2b, (int)((size_t)NE * DIM * HID / 4));
}

__global__ void router_kernel(const float* __restrict__ x,
                              const float* __restrict__ rw,
                              const float* __restrict__ rb) {
    __shared__ float srw[NE * DIM];
    int tid = threadIdx.x;
    for (int i = tid; i < NE * DIM; i += 256) srw[i] = rw[i];
    __syncthreads();
    int warp = tid >> 5, lane = tid & 31;
    int t = blockIdx.x * 8 + warp;
    float xr[32];
#pragma unroll
    for (int i = 0; i < 32; i++) xr[i] = x[(size_t)t * DIM + i * 32 + lane];
    float lg[NE];
#pragma unroll
    for (int e = 0; e < NE; e++) {
        float s = 0.f;
#pragma unroll
        for (int i = 0; i < 32; i++) s += xr[i] * srw[e * DIM + i * 32 + lane];
#pragma unroll
        for (int o = 16; o > 0; o >>= 1) s += __shfl_xor_sync(0xffffffffu, s, o);
        lg[e] = s + rb[e];
    }
    if (lane == 0) {
        int i0 = 0;
#pragma unroll
        for (int e = 1; e < NE; e++) if (lg[e] > lg[i0]) i0 = e;
        int i1 = (i0 == 0) ? 1 : 0;
#pragma unroll
        for (int e = 0; e < NE; e++) {
            if (e == i0) continue;
            if (lg[e] > lg[i1]) i1 = e;
        }
        float e1 = __expf(lg[i1] - lg[i0]);
        g_gate[2 * t]     = 1.f / (1.f + e1);
        g_gate[2 * t + 1] = e1 / (1.f + e1);
        int pos0 = atomicAdd(&g_count[i0], 1);
        g_pairlist[i0 * PAIRS + pos0] = 2 * t;
        int pos1 = atomicAdd(&g_count[i1], 1);
        g_pairlist[i1 * PAIRS + pos1] = 2 * t + 1;
    }
}

// 2-stage mainloop, 64x64 warp tile: per ks, 8 LDSM4 feed 32 independent MMAs.
// fill(kt+1) overlaps compute(kt); buffer safety via this iteration's barrier.
#define GEMM_MAINLOOP(NKC)                                                          \
    FILL(0, 0);                                                                     \
    for (int kt = 0; kt < (NKC); kt++) {                                            \
        int buf = kt & 1;                                                           \
        CP_WAIT0();                                                                 \
        __syncthreads();                                                            \
        if (kt + 1 < (NKC)) FILL(buf ^ 1, kt + 1);                                  \
        uint32_t ab = aBase + buf * ABUF_A, bb = bBase + buf * ABUF_B;              \
        _Pragma("unroll")                                                           \
        for (int ks = 0; ks < 4; ks++) {                                            \
            uint32_t fa[4][4], fb[4][4];                                            \
            _Pragma("unroll")                                                       \
            for (int r = 0; r < 4; r++) LDSM4(fa[r], ab + r * 16 * ROWB + ks * 32); \
            _Pragma("unroll")                                                       \
            for (int r = 0; r < 4; r++) LDSM4(fb[r], bb + r * 16 * ROWB + ks * 32); \
            _Pragma("unroll")                                                       \
            for (int mi = 0; mi < 4; mi++)                                          \
                _Pragma("unroll")                                                   \
                for (int f = 0; f < 8; f++)                                         \
                    mma_f16(acc[mi][f], fa[mi], fb[f >> 1][f & 1],                  \
                            fb[f >> 1][(f & 1) + 2]);                               \
        }                                                                           \
    }

// ---------------- GEMM1: h = swiglu(x @ w1^T + b1); tile 128M x 128 hidden cols ----------------
__global__ void __launch_bounds__(256, 1) gemm1_kernel(const float* __restrict__ b1) {
    extern __shared__ __align__(1024) char sm[];
    uint32_t sb = smem_u32(sm);
    int tid = threadIdx.x;
    int m0 = 0, cnt = 0;
    int e = tile_map(blockIdx.x, m0, cnt);
    if (e < 0) return;
    int rows = min(TM, cnt - m0);
    int n0   = blockIdx.y * 128;   // hidden-col base

    int*   sp    = (int*)(sm + OFF_SP);
    float* sbias = (float*)(sm + OFF_BIAS);
    if (tid < TM) sp[tid] = (tid < rows) ? g_pairlist[e * PAIRS + m0 + tid] : -1;
    if (tid < 128) {
        sbias[tid]       = b1[(size_t)e * H2 + n0 + tid];          // gate bias
        sbias[128 + tid] = b1[(size_t)e * H2 + HID + n0 + tid];    // up bias
    }
    __syncthreads();

    int kk = tid & 7, fr = tid >> 3;
    const __half* asrc[4]; int asz[4];
#pragma unroll
    for (int i = 0; i < 4; i++) {
        int p = sp[fr + 32 * i];
        asrc[i] = g_xb + (size_t)((p >= 0) ? (p >> 1) : 0) * DIM + kk * 8;
        asz[i]  = (p >= 0) ? 16 : 0;
    }
    // B rows r = fr + 32i, i 0..7: global w1 row = n0 + (i>>1)*32 + fr + (i&1)*HID
    const __half* bsrc0 = g_w1b + (size_t)e * H2 * DIM + (size_t)(n0 + fr) * DIM + kk * 8;
    uint32_t adst = sb + OFF_A + fr * ROWB + kk * 16;
    uint32_t bdst = sb + OFF_B + fr * ROWB + kk * 16;

#define FILL(bufi, ktv) do {                                                        \
    uint32_t ao = (bufi) * (uint32_t)ABUF_A, bo = (bufi) * (uint32_t)ABUF_B;        \
    int ks = (ktv) * KC;                                                            \
    _Pragma("unroll") for (int i = 0; i < 4; i++)                                   \
        cp16(adst + ao + i * 32 * ROWB, asrc[i] + ks, asz[i]);                      \
    _Pragma("unroll") for (int i = 0; i < 8; i++)                                   \
        cp16(bdst + bo + i * 32 * ROWB,                                             \
             bsrc0 + ((size_t)((i >> 1) * 32) + (size_t)(i & 1) * HID) * DIM + ks,  \
             16);                                                                   \
    CP_COMMIT(); } while (0)

    float acc[4][8][4];
#pragma unroll
    for (int mi = 0; mi < 4; mi++)
#pragma unroll
        for (int f = 0; f < 8; f++)
#pragma unroll
            for (int q = 0; q < 4; q++) acc[mi][f][q] = 0.f;

    int warp = tid >> 5, lane = tid & 31;
    int wm = warp >> 2, wn = warp & 3;
    uint32_t lrow = lane & 15, lko = (lane >> 4) * 16;
    uint32_t aBase = sb + OFF_A + (wm * 64 + lrow) * ROWB + lko;
    uint32_t bBase = sb + OFF_B + (wn * 64 + lrow) * ROWB + lko;

    GEMM_MAINLOOP(NK1)
#undef FILL

    // epilogue: nj 0-3 gate, nj 4-7 up (same cols); fused swiglu -> fp16 hidden
    int g = lane >> 2, tg = lane & 3;
#pragma unroll
    for (int mi = 0; mi < 4; mi++) {
        int rb = wm * 64 + mi * 16 + g;
#pragma unroll
        for (int f = 0; f < 4; f++) {
            int jj = wn * 32 + f * 8 + 2 * tg;        // 0..127 within tile
            float bg0 = sbias[jj],       bg1 = sbias[jj + 1];
            float bu0 = sbias[128 + jj], bu1 = sbias[128 + jj + 1];
            int j = n0 + jj;
            if (rb < rows) {
                int p = sp[rb];
                float ga = acc[mi][f][0] + bg0, ua = acc[mi][f + 4][0] + bu0;
                float gb = acc[mi][f][1] + bg1, ub = acc[mi][f + 4][1] + bu1;
                float h0 = ga / (1.f + __expf(-ga)) * ua;
                float h1 = gb / (1.f + __expf(-gb)) * ub;
                *(__half2*)&g_hbuf[(size_t)p * HID + j] = __floats2half2_rn(h0, h1);
            }
            if (rb + 8 < rows) {
                int p = sp[rb + 8];
                float ga = acc[mi][f][2] + bg0, ua = acc[mi][f + 4][2] + bu0;
                float gb = acc[mi][f][3] + bg1, ub = acc[mi][f + 4][3] + bu1;
                float h0 = ga / (1.f + __expf(-ga)) * ua;
                float h1 = gb / (1.f + __expf(-gb)) * ub;
                *(__half2*)&g_hbuf[(size_t)p * HID + j] = __floats2half2_rn(h0, h1);
            }
        }
    }
}

// ---------------- GEMM2: out += gate * (h @ w2^T + b2); tile 128M x 256N ----------------
__global__ void __launch_bounds__(256, 1) gemm2_kernel(const float* __restrict__ b2,
                                                       float* __restrict__ out) {
    extern __shared__ __align__(1024) char sm[];
    uint32_t sb = smem_u32(sm);
    int tid = threadIdx.x;
    int m0 = 0, cnt = 0;
    int e = tile_map(blockIdx.x, m0, cnt);
    if (e < 0) return;
    int rows = min(TM, cnt - m0);
    int n0   = blockIdx.y * 256;

    int*   sp    = (int*)(sm + OFF_SP);
    float* sbias = (float*)(sm + OFF_BIAS);
    if (tid < TM) sp[tid] = (tid < rows) ? g_pairlist[e * PAIRS + m0 + tid] : -1;
    sbias[tid] = b2[(size_t)e * DIM + n0 + tid];   // 256 biases
    __syncthreads();

    int kk = tid & 7, fr = tid >> 3;
    const __half* asrc[4]; int asz[4];
#pragma unroll
    for (int i = 0; i < 4; i++) {
        int p = sp[fr + 32 * i];
        asrc[i] = g_hbuf + (size_t)((p >= 0) ? p : 0) * HID + kk * 8;
        asz[i]  = (p >= 0) ? 16 : 0;
    }
    const __half* bsrc0 = g_w2b + (size_t)e * DIM * HID + (size_t)(n0 + fr) * HID + kk * 8;
    uint32_t adst = sb + OFF_A + fr * ROWB + kk * 16;
    uint32_t bdst = sb + OFF_B + fr * ROWB + kk * 16;

#define FILL(bufi, ktv) do {                                                        \
    uint32_t ao = (bufi) * (uint32_t)ABUF_A, bo = (bufi) * (uint32_t)ABUF_B;        \
    int ks = (ktv) * KC;                                                            \
    _Pragma("unroll") for (int i = 0; i < 4; i++)                                   \
        cp16(adst + ao + i * 32 * ROWB, asrc[i] + ks, asz[i]);                      \
    _Pragma("unroll") for (int i = 0; i < 8; i++)                                   \
        cp16(bdst + bo + i * 32 * ROWB, bsrc0 + (size_t)(i * 32) * HID + ks, 16);   \
    CP_COMMIT(); } while (0)

    float acc[4][8][4];
#pragma unroll
    for (int mi = 0; mi < 4; mi++)
#pragma unroll
        for (int f = 0; f < 8; f++)
#pragma unroll
            for (int q = 0; q < 4; q++) acc[mi][f][q] = 0.f;

    int warp = tid >> 5, lane = tid & 31;
    int wm = warp >> 2, wn = warp & 3;
    uint32_t lrow = lane & 15, lko = (lane >> 4) * 16;
    uint32_t aBase = sb + OFF_A + (wm * 64 + lrow) * ROWB + lko;
    uint32_t bBase = sb + OFF_B + (wn * 64 + lrow) * ROWB + lko;

    GEMM_MAINLOOP(NK2)
#undef FILL

    // epilogue: deterministic 2-way atomic combine
    int g = lane >> 2, tg = lane & 3;
#pragma unroll
    for (int mi = 0; mi < 4; mi++) {
        int rb = wm * 64 + mi * 16 + g;
#pragma unroll
        for (int f = 0; f < 8; f++) {
            int jj = wn * 64 + f * 8 + 2 * tg;     // 0..255 within tile
            int j = n0 + jj;
            float bb0 = sbias[jj], bb1 = sbias[jj + 1];
            if (rb < rows) {
                int p = sp[rb];
                int t = p >> 1;
                float w = g_gate[p];
                atomicAdd(&out[(size_t)t * DIM + j],     (acc[mi][f][0] + bb0) * w);
                atomicAdd(&out[(size_t)t * DIM + j + 1], (acc[mi][f][1] + bb1) * w);
            }
            if (rb + 8 < rows) {
                int p = sp[rb + 8];
                int t = p >> 1;
                float w = g_gate[p];
                atomicAdd(&out[(size_t)t * DIM + j],     (acc[mi][f][2] + bb0) * w);
                atomicAdd(&out[(size_t)t * DIM + j + 1], (acc[mi][f][3] + bb1) * w);
            }
        }
    }
}

// ---------------- launch: 4 kernels; gemm2 at slot 3 (ncu capture slot) ----------------
extern "C" void kernel_launch(void* const* d_in, const int* in_sizes, int n_in,
                              void* d_out, int out_size) {
    const float* x  = (const float*)d_in[0];
    const float* rw = (const float*)d_in[1];
    const float* rb = (const float*)d_in[2];
    const float* w1 = (const float*)d_in[3];
    const float* b1 = (const float*)d_in[4];
    const float* w2 = (const float*)d_in[5];
    const float* b2 = (const float*)d_in[6];
    float* out = (float*)d_out;

    cudaFuncSetAttribute(gemm1_kernel, cudaFuncAttributeMaxDynamicSharedMemorySize, SMEM_TOTAL);
    cudaFuncSetAttribute(gemm2_kernel, cudaFuncAttributeMaxDynamicSharedMemorySize, SMEM_TOTAL);

    prep_kernel<<<2048, 256>>>(x, w1, w2, out, out_size / 4);               // idx 0
    router_kernel<<<T_TOKENS / 8, 256>>>(x, rw, rb);                        // idx 1
    gemm1_kernel<<<dim3(MAXTILES, HID / 128), 256, SMEM_TOTAL>>>(b1);       // idx 2
    gemm2_kernel<<<dim3(MAXTILES, DIM / 256), 256, SMEM_TOTAL>>>(b2, out);  // idx 3 (ncu target)
}

// round 12
// speedup vs baseline: 1.2020x; 1.1338x over previous
#include <cuda_runtime.h>
#include <cuda_fp16.h>
#include <cstdint>

#define T_TOKENS 8192
#define DIM      1024
#define HID      4096
#define H2       8192
#define NE       8
#define PAIRS    16384
#define TM       128
#define KC       64              // K halves per chunk (128B row)
#define ROWB     144             // padded row stride (conflict-free ldmatrix)
#define MAXTILES 136
#define NK1      (DIM/KC)        // 16
#define NK2      (HID/KC)        // 64
#define NSTG     3               // cp.async pipeline stages (R12: 2 -> 3)

// dynamic smem layout (per CTA) — 3-stage, 2 CTA/SM (220KB/SM < 228KB)
#define OFF_SP   0
#define OFF_BIAS 512
#define OFF_A    2048
#define ABUF     (128*ROWB)      // 18432 per stage (A and B each)
#define OFF_B    (OFF_A + NSTG*ABUF)
#define SMEM_TOTAL (OFF_B + NSTG*ABUF)   // 112640

// ---------------- device scratch ----------------
__device__ float  g_gate[PAIRS];
__device__ int    g_pairlist[NE * PAIRS];
__device__ int    g_count[NE];
__device__ __half g_xb[T_TOKENS * DIM];
__device__ __half g_w1b[(size_t)NE * H2 * DIM];
__device__ __half g_w2b[(size_t)NE * DIM * HID];
__device__ __half g_hbuf[(size_t)PAIRS * HID];

// ---------------- helpers ----------------
__device__ __forceinline__ uint32_t smem_u32(const void* p) {
    return (uint32_t)__cvta_generic_to_shared(p);
}
__device__ __forceinline__ void cp16(uint32_t dst, const void* src, int sz) {
    asm volatile("cp.async.cg.shared.global [%0], [%1], 16, %2;\n" :: "r"(dst), "l"(src), "r"(sz));
}
#define CP_COMMIT() asm volatile("cp.async.commit_group;\n")
#define CP_WAIT1()  asm volatile("cp.async.wait_group 1;\n")
#define CP_WAIT0()  asm volatile("cp.async.wait_group 0;\n")

#define LDSM4(r, addr) \
    asm volatile("ldmatrix.sync.aligned.m8n8.x4.shared.b16 {%0,%1,%2,%3}, [%4];" \
        : "=r"((r)[0]), "=r"((r)[1]), "=r"((r)[2]), "=r"((r)[3]) : "r"(addr))

__device__ __forceinline__ void mma_f16(float c[4], const uint32_t a[4],
                                        uint32_t b0, uint32_t b1) {
    asm volatile(
        "mma.sync.aligned.m16n8k16.row.col.f32.f16.f16.f32 "
        "{%0,%1,%2,%3}, {%4,%5,%6,%7}, {%8,%9}, {%0,%1,%2,%3};\n"
        : "+f"(c[0]), "+f"(c[1]), "+f"(c[2]), "+f"(c[3])
        : "r"(a[0]), "r"(a[1]), "r"(a[2]), "r"(a[3]), "r"(b0), "r"(b1));
}

// map tile index -> (expert, m0); returns expert or -1
__device__ __forceinline__ int tile_map(int bx, int& m0, int& cnt) {
    int off = 0, e = -1;
#pragma unroll
    for (int i = 0; i < NE; i++) {
        int c = g_count[i];
        int t = (c + TM - 1) / TM;
        if (e < 0 && bx < off + t) { e = i; m0 = (bx - off) * TM; cnt = c; }
        off += t;
    }
    return e;
}

// ---------------- fused prep: counter clear + out zero + all fp32->fp16 converts ----------------
__device__ __forceinline__ void f2h_body(const float4* __restrict__ src,
                                         float2* __restrict__ dst, int n4) {
    int stride = gridDim.x * blockDim.x;
    for (int i = blockIdx.x * blockDim.x + threadIdx.x; i < n4; i += stride) {
        float4 v = src[i];
        union { __half2 h2[2]; float2 f; } u;
        u.h2[0] = __float22half2_rn(make_float2(v.x, v.y));
        u.h2[1] = __float22half2_rn(make_float2(v.z, v.w));
        dst[i] = u.f;
    }
}
__global__ void prep_kernel(const float* __restrict__ x,
                            const float* __restrict__ w1,
                            const float* __restrict__ w2,
                            float* __restrict__ out, int out4) {
    if (blockIdx.x == 0 && threadIdx.x < NE) g_count[threadIdx.x] = 0;
    int stride = gridDim.x * blockDim.x;
    float4 z = make_float4(0.f, 0.f, 0.f, 0.f);
    float4* o4 = (float4*)out;
    for (int i = blockIdx.x * blockDim.x + threadIdx.x; i < out4; i += stride) o4[i] = z;
    f2h_body((const float4*)x,  (float2*)g_xb,  T_TOKENS * DIM / 4);
    f2h_body((const float4*)w1, (float2*)g_w1b, (int)((size_t)NE * H2 * DIM / 4));
    f2h_body((const float4*)w2, (float2*)g_w2b, (int)((size_t)NE * DIM * HID / 4));
}

__global__ void router_kernel(const float* __restrict__ x,
                              const float* __restrict__ rw,
                              const float* __restrict__ rb) {
    __shared__ float srw[NE * DIM];
    int tid = threadIdx.x;
    for (int i = tid; i < NE * DIM; i += 256) srw[i] = rw[i];
    __syncthreads();
    int warp = tid >> 5, lane = tid & 31;
    int t = blockIdx.x * 8 + warp;
    float xr[32];
#pragma unroll
    for (int i = 0; i < 32; i++) xr[i] = x[(size_t)t * DIM + i * 32 + lane];
    float lg[NE];
#pragma unroll
    for (int e = 0; e < NE; e++) {
        float s = 0.f;
#pragma unroll
        for (int i = 0; i < 32; i++) s += xr[i] * srw[e * DIM + i * 32 + lane];
#pragma unroll
        for (int o = 16; o > 0; o >>= 1) s += __shfl_xor_sync(0xffffffffu, s, o);
        lg[e] = s + rb[e];
    }
    if (lane == 0) {
        int i0 = 0;
#pragma unroll
        for (int e = 1; e < NE; e++) if (lg[e] > lg[i0]) i0 = e;
        int i1 = (i0 == 0) ? 1 : 0;
#pragma unroll
        for (int e = 0; e < NE; e++) {
            if (e == i0) continue;
            if (lg[e] > lg[i1]) i1 = e;
        }
        float e1 = __expf(lg[i1] - lg[i0]);
        g_gate[2 * t]     = 1.f / (1.f + e1);
        g_gate[2 * t + 1] = e1 / (1.f + e1);
        int pos0 = atomicAdd(&g_count[i0], 1);
        g_pairlist[i0 * PAIRS + pos0] = 2 * t;
        int pos1 = atomicAdd(&g_count[i1], 1);
        g_pairlist[i1 * PAIRS + pos1] = 2 * t + 1;
    }
}

// 3-stage mainloop (2 CTA/SM). Fill(kt+2) is issued two chunk-times before its
// wait, so CP_WAIT1 at chunk kt (drain fill(kt), allow fill(kt+1) in flight)
// is normally already satisfied. Buffer safety: fill(kt+2) overwrites the
// stage computed at kt-1, ordered by this iteration's barrier.
#define GEMM_MAINLOOP(NKC)                                                          \
    FILL(0, 0);                                                                     \
    FILL(1, 1);                                                                     \
    for (int kt = 0; kt < (NKC); kt++) {                                            \
        int buf = kt % NSTG;                                                        \
        if (kt + 1 < (NKC)) CP_WAIT1(); else CP_WAIT0();                            \
        __syncthreads();                                                            \
        if (kt + 2 < (NKC)) FILL((kt + 2) % NSTG, kt + 2);                          \
        uint32_t ab = aBase + buf * ABUF, bb = bBase + buf * ABUF;                  \
        _Pragma("unroll")                                                           \
        for (int ks = 0; ks < 4; ks++) {                                            \
            uint32_t a[2][4], b[4][4];                                              \
            LDSM4(a[0], ab + ks * 32);                                              \
            LDSM4(a[1], ab + 16 * ROWB + ks * 32);                                  \
            _Pragma("unroll")                                                       \
            for (int j = 0; j < 4; j++) LDSM4(b[j], bb + j * 16 * ROWB + ks * 32);  \
            _Pragma("unroll")                                                       \
            for (int f = 0; f < 8; f++) {                                           \
                int j = f >> 1, h = f & 1;                                          \
                mma_f16(acc[0][f], a[0], b[j][h], b[j][h + 2]);                     \
                mma_f16(acc[1][f], a[1], b[j][h], b[j][h + 2]);                     \
            }                                                                       \
        }                                                                           \
    }

// ---------------- GEMM1: h = swiglu(x @ w1^T + b1) ----------------
__global__ void __launch_bounds__(256, 2) gemm1_kernel(const float* __restrict__ b1) {
    extern __shared__ __align__(1024) char sm[];
    uint32_t sb = smem_u32(sm);
    int tid = threadIdx.x;
    int m0 = 0, cnt = 0;
    int e = tile_map(blockIdx.x, m0, cnt);
    if (e < 0) return;
    int rows = min(TM, cnt - m0);
    int n0   = blockIdx.y * 64;

    int*   sp    = (int*)(sm + OFF_SP);
    float* sbias = (float*)(sm + OFF_BIAS);
    if (tid < TM) sp[tid] = (tid < rows) ? g_pairlist[e * PAIRS + m0 + tid] : -1;
    if (tid < 64) {
        sbias[tid]      = b1[(size_t)e * H2 + n0 + tid];
        sbias[64 + tid] = b1[(size_t)e * H2 + HID + n0 + tid];
    }
    __syncthreads();

    int kk = tid & 7, fr = tid >> 3;
    const __half* asrc[4]; int asz[4];
#pragma unroll
    for (int i = 0; i < 4; i++) {
        int p = sp[fr + 32 * i];
        asrc[i] = g_xb + (size_t)((p >= 0) ? (p >> 1) : 0) * DIM + kk * 8;
        asz[i]  = (p >= 0) ? 16 : 0;
    }
    const __half* wb = g_w1b + (size_t)e * H2 * DIM;
    const __half* bsrc[4];
#pragma unroll
    for (int i = 0; i < 4; i++) {
        int grow = n0 + (i >> 1) * 32 + fr + (i & 1) * HID;
        bsrc[i] = wb + (size_t)grow * DIM + kk * 8;
    }
    uint32_t adst = sb + OFF_A + fr * ROWB + kk * 16;
    uint32_t bdst = sb + OFF_B + fr * ROWB + kk * 16;

#define FILL(bufi, ktv) do {                                                   \
    uint32_t ao = (bufi) * (uint32_t)ABUF; int ks = (ktv) * KC;                \
    _Pragma("unroll") for (int i = 0; i < 4; i++)                              \
        cp16(adst + ao + i * 32 * ROWB, asrc[i] + ks, asz[i]);                 \
    _Pragma("unroll") for (int i = 0; i < 4; i++)                              \
        cp16(bdst + ao + i * 32 * ROWB, bsrc[i] + ks, 16);                     \
    CP_COMMIT(); } while (0)

    float acc[2][8][4];
#pragma unroll
    for (int mi = 0; mi < 2; mi++)
#pragma unroll
        for (int f = 0; f < 8; f++)
#pragma unroll
            for (int q = 0; q < 4; q++) acc[mi][f][q] = 0.f;

    int warp = tid >> 5, lane = tid & 31;
    int wm = warp >> 1, wn = warp & 1;
    uint32_t lrow = lane & 15, lko = (lane >> 4) * 16;
    uint32_t aBase = sb + OFF_A + (wm * 32 + lrow) * ROWB + lko;
    uint32_t bBase = sb + OFF_B + (wn * 64 + lrow) * ROWB + lko;

    GEMM_MAINLOOP(NK1)
#undef FILL

    int g = lane >> 2, tg = lane & 3;
#pragma unroll
    for (int mi = 0; mi < 2; mi++) {
        int rb = wm * 32 + mi * 16 + g;
#pragma unroll
        for (int f = 0; f < 4; f++) {
            int jj = wn * 32 + f * 8 + 2 * tg;
            float bg0 = sbias[jj],      bg1 = sbias[jj + 1];
            float bu0 = sbias[64 + jj], bu1 = sbias[64 + jj + 1];
            int j = n0 + jj;
            if (rb < rows) {
                int p = sp[rb];
                float ga = acc[mi][f][0] + bg0, ua = acc[mi][f + 4][0] + bu0;
                float gb = acc[mi][f][1] + bg1, ub = acc[mi][f + 4][1] + bu1;
                float h0 = ga / (1.f + __expf(-ga)) * ua;
                float h1 = gb / (1.f + __expf(-gb)) * ub;
                *(__half2*)&g_hbuf[(size_t)p * HID + j] = __floats2half2_rn(h0, h1);
            }
            if (rb + 8 < rows) {
                int p = sp[rb + 8];
                float ga = acc[mi][f][2] + bg0, ua = acc[mi][f + 4][2] + bu0;
                float gb = acc[mi][f][3] + bg1, ub = acc[mi][f + 4][3] + bu1;
                float h0 = ga / (1.f + __expf(-ga)) * ua;
                float h1 = gb / (1.f + __expf(-gb)) * ub;
                *(__half2*)&g_hbuf[(size_t)p * HID + j] = __floats2half2_rn(h0, h1);
            }
        }
    }
}

// ---------------- GEMM2: out += gate * (h @ w2^T + b2)  (m-fastest grid, R8-proven) ----------------
__global__ void __launch_bounds__(256, 2) gemm2_kernel(const float* __restrict__ b2,
                                                       float* __restrict__ out) {
    extern __shared__ __align__(1024) char sm[];
    uint32_t sb = smem_u32(sm);
    int tid = threadIdx.x;
    int m0 = 0, cnt = 0;
    int e = tile_map(blockIdx.x, m0, cnt);
    if (e < 0) return;
    int rows = min(TM, cnt - m0);
    int n0   = blockIdx.y * 128;

    int*   sp    = (int*)(sm + OFF_SP);
    float* sbias = (float*)(sm + OFF_BIAS);
    if (tid < TM) sp[tid] = (tid < rows) ? g_pairlist[e * PAIRS + m0 + tid] : -1;
    if (tid < 128) sbias[tid] = b2[(size_t)e * DIM + n0 + tid];
    __syncthreads();

    int kk = tid & 7, fr = tid >> 3;
    const __half* asrc[4]; int asz[4];
#pragma unroll
    for (int i = 0; i < 4; i++) {
        int p = sp[fr + 32 * i];
        asrc[i] = g_hbuf + (size_t)((p >= 0) ? p : 0) * HID + kk * 8;
        asz[i]  = (p >= 0) ? 16 : 0;
    }
    const __half* wb = g_w2b + (size_t)e * DIM * HID;
    const __half* bsrc[4];
#pragma unroll
    for (int i = 0; i < 4; i++) bsrc[i] = wb + (size_t)(n0 + fr + 32 * i) * HID + kk * 8;
    uint32_t adst = sb + OFF_A + fr * ROWB + kk * 16;
    uint32_t bdst = sb + OFF_B + fr * ROWB + kk * 16;

#define FILL(bufi, ktv) do {                                                   \
    uint32_t ao = (bufi) * (uint32_t)ABUF; int ks = (ktv) * KC;                \
    _Pragma("unroll") for (int i = 0; i < 4; i++)                              \
        cp16(adst + ao + i * 32 * ROWB, asrc[i] + ks, asz[i]);                 \
    _Pragma("unroll") for (int i = 0; i < 4; i++)                              \
        cp16(bdst + ao + i * 32 * ROWB, bsrc[i] + ks, 16);                     \
    CP_COMMIT(); } while (0)

    float acc[2][8][4];
#pragma unroll
    for (int mi = 0; mi < 2; mi++)
#pragma unroll
        for (int f = 0; f < 8; f++)
#pragma unroll
            for (int q = 0; q < 4; q++) acc[mi][f][q] = 0.f;

    int warp = tid >> 5, lane = tid & 31;
    int wm = warp >> 1, wn = warp & 1;
    uint32_t lrow = lane & 15, lko = (lane >> 4) * 16;
    uint32_t aBase = sb + OFF_A + (wm * 32 + lrow) * ROWB + lko;
    uint32_t bBase = sb + OFF_B + (wn * 64 + lrow) * ROWB + lko;

    GEMM_MAINLOOP(NK2)
#undef FILL

    int g = lane >> 2, tg = lane & 3;
#pragma unroll
    for (int mi = 0; mi < 2; mi++) {
        int rb = wm * 32 + mi * 16 + g;
#pragma unroll
        for (int f = 0; f < 8; f++) {
            int jj = wn * 64 + f * 8 + 2 * tg;
            int j = n0 + jj;
            float bb0 = sbias[jj], bb1 = sbias[jj + 1];
            if (rb < rows) {
                int p = sp[rb];
                int t = p >> 1;
                float w = g_gate[p];
                atomicAdd(&out[(size_t)t * DIM + j],     (acc[mi][f][0] + bb0) * w);
                atomicAdd(&out[(size_t)t * DIM + j + 1], (acc[mi][f][1] + bb1) * w);
            }
            if (rb + 8 < rows) {
                int p = sp[rb + 8];
                int t = p >> 1;
                float w = g_gate[p];
                atomicAdd(&out[(size_t)t * DIM + j],     (acc[mi][f][2] + bb0) * w);
                atomicAdd(&out[(size_t)t * DIM + j + 1], (acc[mi][f][3] + bb1) * w);
            }
        }
    }
}

// ---------------- launch: 4 kernels; gemm2 at slot 3 (ncu capture slot) ----------------
extern "C" void kernel_launch(void* const* d_in, const int* in_sizes, int n_in,
                              void* d_out, int out_size) {
    const float* x  = (const float*)d_in[0];
    const float* rw = (const float*)d_in[1];
    const float* rb = (const float*)d_in[2];
    const float* w1 = (const float*)d_in[3];
    const float* b1 = (const float*)d_in[4];
    const float* w2 = (const float*)d_in[5];
    const float* b2 = (const float*)d_in[6];
    float* out = (float*)d_out;

    cudaFuncSetAttribute(gemm1_kernel, cudaFuncAttributeMaxDynamicSharedMemorySize, SMEM_TOTAL);
    cudaFuncSetAttribute(gemm2_kernel, cudaFuncAttributeMaxDynamicSharedMemorySize, SMEM_TOTAL);

    prep_kernel<<<2048, 256>>>(x, w1, w2, out, out_size / 4);               // idx 0
    router_kernel<<<T_TOKENS / 8, 256>>>(x, rw, rb);                        // idx 1
    gemm1_kernel<<<dim3(MAXTILES, HID / 64), 256, SMEM_TOTAL>>>(b1);        // idx 2
    gemm2_kernel<<<dim3(MAXTILES, DIM / 128), 256, SMEM_TOTAL>>>(b2, out);  // idx 3 (ncu target)
}

// round 13
// speedup vs baseline: 1.2407x; 1.0323x over previous
#include <cuda_runtime.h>
#include <cuda_fp16.h>
#include <cstdint>

#define T_TOKENS 8192
#define DIM      1024
#define HID      4096
#define H2       8192
#define NE       8
#define PAIRS    16384
#define TM       128
#define KC       64              // K halves per chunk (128B row)
#define ROWB     144             // padded row stride (conflict-free ldmatrix)
#define MAXTILES 136
#define NK1      (DIM/KC)        // 16
#define NK2      (HID/KC)        // 64
#define MG       8               // m-tiles per L2 group

// dynamic smem layout (per CTA) — 2-stage (R8-proven)
#define OFF_SP   0
#define OFF_BIAS 512
#define OFF_A    2048
#define ABUF     (128*ROWB)      // 18432 per stage
#define OFF_B    (OFF_A + 2*ABUF)
#define SMEM_TOTAL (OFF_B + 2*ABUF)   // 75776

// ---------------- device scratch ----------------
__device__ float  g_gate[PAIRS];
__device__ int    g_pairlist[NE * PAIRS];
__device__ int    g_count[NE];
__device__ __half g_xb[T_TOKENS * DIM];
__device__ __half g_w1b[(size_t)NE * H2 * DIM];
__device__ __half g_w2b[(size_t)NE * DIM * HID];
__device__ __half g_hbuf[(size_t)PAIRS * HID];

// ---------------- helpers ----------------
__device__ __forceinline__ uint32_t smem_u32(const void* p) {
    return (uint32_t)__cvta_generic_to_shared(p);
}
__device__ __forceinline__ void cp16(uint32_t dst, const void* src, int sz) {
    asm volatile("cp.async.cg.shared.global [%0], [%1], 16, %2;\n" :: "r"(dst), "l"(src), "r"(sz));
}
#define CP_COMMIT() asm volatile("cp.async.commit_group;\n")
#define CP_WAIT0()  asm volatile("cp.async.wait_group 0;\n")

#define LDSM4(r, addr) \
    asm volatile("ldmatrix.sync.aligned.m8n8.x4.shared.b16 {%0,%1,%2,%3}, [%4];" \
        : "=r"((r)[0]), "=r"((r)[1]), "=r"((r)[2]), "=r"((r)[3]) : "r"(addr))

__device__ __forceinline__ void mma_f16(float c[4], const uint32_t a[4],
                                        uint32_t b0, uint32_t b1) {
    asm volatile(
        "mma.sync.aligned.m16n8k16.row.col.f32.f16.f16.f32 "
        "{%0,%1,%2,%3}, {%4,%5,%6,%7}, {%8,%9}, {%0,%1,%2,%3};\n"
        : "+f"(c[0]), "+f"(c[1]), "+f"(c[2]), "+f"(c[3])
        : "r"(a[0]), "r"(a[1]), "r"(a[2]), "r"(a[3]), "r"(b0), "r"(b1));
}

// map m-tile index -> (expert, m0); returns expert or -1
__device__ __forceinline__ int tile_map(int bx, int& m0, int& cnt) {
    int off = 0, e = -1;
#pragma unroll
    for (int i = 0; i < NE; i++) {
        int c = g_count[i];
        int t = (c + TM - 1) / TM;
        if (e < 0 && bx < off + t) { e = i; m0 = (bx - off) * TM; cnt = c; }
        off += t;
    }
    return e;
}

// ---------------- fused prep: counter clear + out zero + all fp32->fp16 converts ----------------
__device__ __forceinline__ void f2h_body(const float4* __restrict__ src,
                                         float2* __restrict__ dst, int n4) {
    int stride = gridDim.x * blockDim.x;
    for (int i = blockIdx.x * blockDim.x + threadIdx.x; i < n4; i += stride) {
        float4 v = src[i];
        union { __half2 h2[2]; float2 f; } u;
        u.h2[0] = __float22half2_rn(make_float2(v.x, v.y));
        u.h2[1] = __float22half2_rn(make_float2(v.z, v.w));
        dst[i] = u.f;
    }
}
__global__ void prep_kernel(const float* __restrict__ x,
                            const float* __restrict__ w1,
                            const float* __restrict__ w2,
                            float* __restrict__ out, int out4) {
    if (blockIdx.x == 0 && threadIdx.x < NE) g_count[threadIdx.x] = 0;
    int stride = gridDim.x * blockDim.x;
    float4 z = make_float4(0.f, 0.f, 0.f, 0.f);
    float4* o4 = (float4*)out;
    for (int i = blockIdx.x * blockDim.x + threadIdx.x; i < out4; i += stride) o4[i] = z;
    f2h_body((const float4*)x,  (float2*)g_xb,  T_TOKENS * DIM / 4);
    f2h_body((const float4*)w1, (float2*)g_w1b, (int)((size_t)NE * H2 * DIM / 4));
    f2h_body((const float4*)w2, (float2*)g_w2b, (int)((size_t)NE * DIM * HID / 4));
}

__global__ void router_kernel(const float* __restrict__ x,
                              const float* __restrict__ rw,
                              const float* __restrict__ rb) {
    __shared__ float srw[NE * DIM];
    int tid = threadIdx.x;
    for (int i = tid; i < NE * DIM; i += 256) srw[i] = rw[i];
    __syncthreads();
    int warp = tid >> 5, lane = tid & 31;
    int t = blockIdx.x * 8 + warp;
    float xr[32];
#pragma unroll
    for (int i = 0; i < 32; i++) xr[i] = x[(size_t)t * DIM + i * 32 + lane];
    float lg[NE];
#pragma unroll
    for (int e = 0; e < NE; e++) {
        float s = 0.f;
#pragma unroll
        for (int i = 0; i < 32; i++) s += xr[i] * srw[e * DIM + i * 32 + lane];
#pragma unroll
        for (int o = 16; o > 0; o >>= 1) s += __shfl_xor_sync(0xffffffffu, s, o);
        lg[e] = s + rb[e];
    }
    if (lane == 0) {
        int i0 = 0;
#pragma unroll
        for (int e = 1; e < NE; e++) if (lg[e] > lg[i0]) i0 = e;
        int i1 = (i0 == 0) ? 1 : 0;
#pragma unroll
        for (int e = 0; e < NE; e++) {
            if (e == i0) continue;
            if (lg[e] > lg[i1]) i1 = e;
        }
        float e1 = __expf(lg[i1] - lg[i0]);
        g_gate[2 * t]     = 1.f / (1.f + e1);
        g_gate[2 * t + 1] = e1 / (1.f + e1);
        int pos0 = atomicAdd(&g_count[i0], 1);
        g_pairlist[i0 * PAIRS + pos0] = 2 * t;
        int pos1 = atomicAdd(&g_count[i1], 1);
        g_pairlist[i1 * PAIRS + pos1] = 2 * t + 1;
    }
}

// 2-stage mainloop (R8-proven): one barrier per K-chunk; fill(kt+1) overlaps
// compute(kt).
#define GEMM_MAINLOOP(NKC)                                                          \
    FILL(0, 0);                                                                     \
    for (int kt = 0; kt < (NKC); kt++) {                                            \
        int buf = kt & 1;                                                           \
        CP_WAIT0();                                                                 \
        __syncthreads();                                                            \
        if (kt + 1 < (NKC)) FILL(buf ^ 1, kt + 1);                                  \
        uint32_t ab = aBase + buf * ABUF, bb = bBase + buf * ABUF;                  \
        _Pragma("unroll")                                                           \
        for (int ks = 0; ks < 4; ks++) {                                            \
            uint32_t a[2][4], b[4][4];                                              \
            LDSM4(a[0], ab + ks * 32);                                              \
            LDSM4(a[1], ab + 16 * ROWB + ks * 32);                                  \
            _Pragma("unroll")                                                       \
            for (int j = 0; j < 4; j++) LDSM4(b[j], bb + j * 16 * ROWB + ks * 32);  \
            _Pragma("unroll")                                                       \
            for (int f = 0; f < 8; f++) {                                           \
                int j = f >> 1, h = f & 1;                                          \
                mma_f16(acc[0][f], a[0], b[j][h], b[j][h + 2]);                     \
                mma_f16(acc[1][f], a[1], b[j][h], b[j][h + 2]);                     \
            }                                                                       \
        }                                                                           \
    }

// ---------------- GEMM1: h = swiglu(x @ w1^T + b1) ----------------
// L2-blocked rasterization: 1D grid ordered (m-group of MG) x (all 64 n) x (m in group)
__global__ void __launch_bounds__(256, 2) gemm1_kernel(const float* __restrict__ b1) {
    extern __shared__ __align__(1024) char sm[];
    uint32_t sb = smem_u32(sm);
    int tid = threadIdx.x;
    int t1  = blockIdx.x;
    int grp = t1 / (MG * (HID / 64));
    int rem = t1 % (MG * (HID / 64));
    int nt  = rem / MG;
    int mtile = grp * MG + (rem % MG);
    int m0 = 0, cnt = 0;
    int e = tile_map(mtile, m0, cnt);
    if (e < 0) return;
    int rows = min(TM, cnt - m0);
    int n0   = nt * 64;

    int*   sp    = (int*)(sm + OFF_SP);
    float* sbias = (float*)(sm + OFF_BIAS);
    if (tid < TM) sp[tid] = (tid < rows) ? g_pairlist[e * PAIRS + m0 + tid] : -1;
    if (tid < 64) {
        sbias[tid]      = b1[(size_t)e * H2 + n0 + tid];
        sbias[64 + tid] = b1[(size_t)e * H2 + HID + n0 + tid];
    }
    __syncthreads();

    int kk = tid & 7, fr = tid >> 3;
    const __half* asrc[4]; int asz[4];
#pragma unroll
    for (int i = 0; i < 4; i++) {
        int p = sp[fr + 32 * i];
        asrc[i] = g_xb + (size_t)((p >= 0) ? (p >> 1) : 0) * DIM + kk * 8;
        asz[i]  = (p >= 0) ? 16 : 0;
    }
    const __half* wb = g_w1b + (size_t)e * H2 * DIM;
    const __half* bsrc[4];
#pragma unroll
    for (int i = 0; i < 4; i++) {
        int grow = n0 + (i >> 1) * 32 + fr + (i & 1) * HID;
        bsrc[i] = wb + (size_t)grow * DIM + kk * 8;
    }
    uint32_t adst = sb + OFF_A + fr * ROWB + kk * 16;
    uint32_t bdst = sb + OFF_B + fr * ROWB + kk * 16;

#define FILL(bufi, ktv) do {                                                   \
    uint32_t ao = (bufi) * (uint32_t)ABUF; int ks = (ktv) * KC;                \
    _Pragma("unroll") for (int i = 0; i < 4; i++)                              \
        cp16(adst + ao + i * 32 * ROWB, asrc[i] + ks, asz[i]);                 \
    _Pragma("unroll") for (int i = 0; i < 4; i++)                              \
        cp16(bdst + ao + i * 32 * ROWB, bsrc[i] + ks, 16);                     \
    CP_COMMIT(); } while (0)

    float acc[2][8][4];
#pragma unroll
    for (int mi = 0; mi < 2; mi++)
#pragma unroll
        for (int f = 0; f < 8; f++)
#pragma unroll
            for (int q = 0; q < 4; q++) acc[mi][f][q] = 0.f;

    int warp = tid >> 5, lane = tid & 31;
    int wm = warp >> 1, wn = warp & 1;
    uint32_t lrow = lane & 15, lko = (lane >> 4) * 16;
    uint32_t aBase = sb + OFF_A + (wm * 32 + lrow) * ROWB + lko;
    uint32_t bBase = sb + OFF_B + (wn * 64 + lrow) * ROWB + lko;

    GEMM_MAINLOOP(NK1)
#undef FILL

    int g = lane >> 2, tg = lane & 3;
#pragma unroll
    for (int mi = 0; mi < 2; mi++) {
        int rb = wm * 32 + mi * 16 + g;
#pragma unroll
        for (int f = 0; f < 4; f++) {
            int jj = wn * 32 + f * 8 + 2 * tg;
            float bg0 = sbias[jj],      bg1 = sbias[jj + 1];
            float bu0 = sbias[64 + jj], bu1 = sbias[64 + jj + 1];
            int j = n0 + jj;
            if (rb < rows) {
                int p = sp[rb];
                float ga = acc[mi][f][0] + bg0, ua = acc[mi][f + 4][0] + bu0;
                float gb = acc[mi][f][1] + bg1, ub = acc[mi][f + 4][1] + bu1;
                float h0 = ga / (1.f + __expf(-ga)) * ua;
                float h1 = gb / (1.f + __expf(-gb)) * ub;
                *(__half2*)&g_hbuf[(size_t)p * HID + j] = __floats2half2_rn(h0, h1);
            }
            if (rb + 8 < rows) {
                int p = sp[rb + 8];
                float ga = acc[mi][f][2] + bg0, ua = acc[mi][f + 4][2] + bu0;
                float gb = acc[mi][f][3] + bg1, ub = acc[mi][f + 4][3] + bu1;
                float h0 = ga / (1.f + __expf(-ga)) * ua;
                float h1 = gb / (1.f + __expf(-gb)) * ub;
                *(__half2*)&g_hbuf[(size_t)p * HID + j] = __floats2half2_rn(h0, h1);
            }
        }
    }
}

// ---------------- GEMM2: out += gate * (h @ w2^T + b2) ----------------
// L2-blocked rasterization: (m-group of MG) x (all 8 n) x (m in group)
__global__ void __launch_bounds__(256, 2) gemm2_kernel(const float* __restrict__ b2,
                                                       float* __restrict__ out) {
    extern __shared__ __align__(1024) char sm[];
    uint32_t sb = smem_u32(sm);
    int tid = threadIdx.x;
    int t1  = blockIdx.x;
    int grp = t1 / (MG * (DIM / 128));
    int rem = t1 % (MG * (DIM / 128));
    int nt  = rem / MG;
    int mtile = grp * MG + (rem % MG);
    int m0 = 0, cnt = 0;
    int e = tile_map(mtile, m0, cnt);
    if (e < 0) return;
    int rows = min(TM, cnt - m0);
    int n0   = nt * 128;

    int*   sp    = (int*)(sm + OFF_SP);
    float* sbias = (float*)(sm + OFF_BIAS);
    if (tid < TM) sp[tid] = (tid < rows) ? g_pairlist[e * PAIRS + m0 + tid] : -1;
    if (tid < 128) sbias[tid] = b2[(size_t)e * DIM + n0 + tid];
    __syncthreads();

    int kk = tid & 7, fr = tid >> 3;
    const __half* asrc[4]; int asz[4];
#pragma unroll
    for (int i = 0; i < 4; i++) {
        int p = sp[fr + 32 * i];
        asrc[i] = g_hbuf + (size_t)((p >= 0) ? p : 0) * HID + kk * 8;
        asz[i]  = (p >= 0) ? 16 : 0;
    }
    const __half* wb = g_w2b + (size_t)e * DIM * HID;
    const __half* bsrc[4];
#pragma unroll
    for (int i = 0; i < 4; i++) bsrc[i] = wb + (size_t)(n0 + fr + 32 * i) * HID + kk * 8;
    uint32_t adst = sb + OFF_A + fr * ROWB + kk * 16;
    uint32_t bdst = sb + OFF_B + fr * ROWB + kk * 16;

#define FILL(bufi, ktv) do {                                                   \
    uint32_t ao = (bufi) * (uint32_t)ABUF; int ks = (ktv) * KC;                \
    _Pragma("unroll") for (int i = 0; i < 4; i++)                              \
        cp16(adst + ao + i * 32 * ROWB, asrc[i] + ks, asz[i]);                 \
    _Pragma("unroll") for (int i = 0; i < 4; i++)                              \
        cp16(bdst + ao + i * 32 * ROWB, bsrc[i] + ks, 16);                     \
    CP_COMMIT(); } while (0)

    float acc[2][8][4];
#pragma unroll
    for (int mi = 0; mi < 2; mi++)
#pragma unroll
        for (int f = 0; f < 8; f++)
#pragma unroll
            for (int q = 0; q < 4; q++) acc[mi][f][q] = 0.f;

    int warp = tid >> 5, lane = tid & 31;
    int wm = warp >> 1, wn = warp & 1;
    uint32_t lrow = lane & 15, lko = (lane >> 4) * 16;
    uint32_t aBase = sb + OFF_A + (wm * 32 + lrow) * ROWB + lko;
    uint32_t bBase = sb + OFF_B + (wn * 64 + lrow) * ROWB + lko;

    GEMM_MAINLOOP(NK2)
#undef FILL

    int g = lane >> 2, tg = lane & 3;
#pragma unroll
    for (int mi = 0; mi < 2; mi++) {
        int rb = wm * 32 + mi * 16 + g;
#pragma unroll
        for (int f = 0; f < 8; f++) {
            int jj = wn * 64 + f * 8 + 2 * tg;
            int j = n0 + jj;
            float bb0 = sbias[jj], bb1 = sbias[jj + 1];
            if (rb < rows) {
                int p = sp[rb];
                int t = p >> 1;
                float w = g_gate[p];
                atomicAdd(&out[(size_t)t * DIM + j],     (acc[mi][f][0] + bb0) * w);
                atomicAdd(&out[(size_t)t * DIM + j + 1], (acc[mi][f][1] + bb1) * w);
            }
            if (rb + 8 < rows) {
                int p = sp[rb + 8];
                int t = p >> 1;
                float w = g_gate[p];
                atomicAdd(&out[(size_t)t * DIM + j],     (acc[mi][f][2] + bb0) * w);
                atomicAdd(&out[(size_t)t * DIM + j + 1], (acc[mi][f][3] + bb1) * w);
            }
        }
    }
}

// ---------------- launch: 4 kernels; gemm2 at slot 3 (ncu capture slot) ----------------
extern "C" void kernel_launch(void* const* d_in, const int* in_sizes, int n_in,
                              void* d_out, int out_size) {
    const float* x  = (const float*)d_in[0];
    const float* rw = (const float*)d_in[1];
    const float* rb = (const float*)d_in[2];
    const float* w1 = (const float*)d_in[3];
    const float* b1 = (const float*)d_in[4];
    const float* w2 = (const float*)d_in[5];
    const float* b2 = (const float*)d_in[6];
    float* out = (float*)d_out;

    cudaFuncSetAttribute(gemm1_kernel, cudaFuncAttributeMaxDynamicSharedMemorySize, SMEM_TOTAL);
    cudaFuncSetAttribute(gemm2_kernel, cudaFuncAttributeMaxDynamicSharedMemorySize, SMEM_TOTAL);

    prep_kernel<<<2048, 256>>>(x, w1, w2, out, out_size / 4);            // idx 0
    router_kernel<<<T_TOKENS / 8, 256>>>(x, rw, rb);                     // idx 1
    gemm1_kernel<<<MAXTILES * (HID / 64), 256, SMEM_TOTAL>>>(b1);        // idx 2
    gemm2_kernel<<<MAXTILES * (DIM / 128), 256, SMEM_TOTAL>>>(b2, out);  // idx 3 (ncu target)
}

// round 14
// speedup vs baseline: 1.2577x; 1.0137x over previous
#include <cuda_runtime.h>
#include <cuda_fp16.h>
#include <cstdint>

#define T_TOKENS 8192
#define DIM      1024
#define HID      4096
#define H2       8192
#define NE       8
#define PAIRS    16384
#define TM       128
#define KC       64              // K halves per chunk (128B row)
#define ROWB     144             // padded row stride (conflict-free ldmatrix)
#define MAXTILES 136
#define NK1      (DIM/KC)        // 16
#define NK2      (HID/KC)        // 64

// dynamic smem layout (per CTA) — 2-stage (R8-proven)
#define OFF_SP   0
#define OFF_BIAS 512
#define OFF_A    2048
#define ABUF     (128*ROWB)      // 18432 per stage
#define OFF_B    (OFF_A + 2*ABUF)
#define SMEM_TOTAL (OFF_B + 2*ABUF)   // 75776

// ---------------- device scratch ----------------
__device__ float  g_gate[PAIRS];
__device__ int    g_pairlist[NE * PAIRS];
__device__ int    g_count[NE];
__device__ __half g_xb[T_TOKENS * DIM];
__device__ __half g_w1b[(size_t)NE * H2 * DIM];
__device__ __half g_w2b[(size_t)NE * DIM * HID];
__device__ __half g_hbuf[(size_t)PAIRS * HID];

// ---------------- helpers ----------------
__device__ __forceinline__ uint32_t smem_u32(const void* p) {
    return (uint32_t)__cvta_generic_to_shared(p);
}
__device__ __forceinline__ void cp16(uint32_t dst, const void* src, int sz) {
    asm volatile("cp.async.cg.shared.global [%0], [%1], 16, %2;\n" :: "r"(dst), "l"(src), "r"(sz));
}
#define CP_COMMIT() asm volatile("cp.async.commit_group;\n")
#define CP_WAIT0()  asm volatile("cp.async.wait_group 0;\n")

#define LDSM4(r, addr) \
    asm volatile("ldmatrix.sync.aligned.m8n8.x4.shared.b16 {%0,%1,%2,%3}, [%4];" \
        : "=r"((r)[0]), "=r"((r)[1]), "=r"((r)[2]), "=r"((r)[3]) : "r"(addr))

__device__ __forceinline__ void mma_f16(float c[4], const uint32_t a[4],
                                        uint32_t b0, uint32_t b1) {
    asm volatile(
        "mma.sync.aligned.m16n8k16.row.col.f32.f16.f16.f32 "
        "{%0,%1,%2,%3}, {%4,%5,%6,%7}, {%8,%9}, {%0,%1,%2,%3};\n"
        : "+f"(c[0]), "+f"(c[1]), "+f"(c[2]), "+f"(c[3])
        : "r"(a[0]), "r"(a[1]), "r"(a[2]), "r"(a[3]), "r"(b0), "r"(b1));
}

// map m-tile index -> (expert, m0); returns expert or -1
__device__ __forceinline__ int tile_map(int bx, int& m0, int& cnt) {
    int off = 0, e = -1;
#pragma unroll
    for (int i = 0; i < NE; i++) {
        int c = g_count[i];
        int t = (c + TM - 1) / TM;
        if (e < 0 && bx < off + t) { e = i; m0 = (bx - off) * TM; cnt = c; }
        off += t;
    }
    return e;
}

// ---------------- converts / zero / router ----------------
__device__ __forceinline__ void f2h_body(const float4* __restrict__ src,
                                         float2* __restrict__ dst, int n4) {
    int stride = gridDim.x * blockDim.x;
    for (int i = blockIdx.x * blockDim.x + threadIdx.x; i < n4; i += stride) {
        float4 v = src[i];
        union { __half2 h2[2]; float2 f; } u;
        u.h2[0] = __float22half2_rn(make_float2(v.x, v.y));
        u.h2[1] = __float22half2_rn(make_float2(v.z, v.w));
        dst[i] = u.f;
    }
}
__global__ void cvt_xw1_kernel(const float* __restrict__ x,
                               const float* __restrict__ w1) {
    f2h_body((const float4*)x,  (float2*)g_xb,  T_TOKENS * DIM / 4);
    f2h_body((const float4*)w1, (float2*)g_w1b, (int)((size_t)NE * H2 * DIM / 4));
}
__global__ void cvt_w2_kernel(const float* __restrict__ w2) {
    f2h_body((const float4*)w2, (float2*)g_w2b, (int)((size_t)NE * DIM * HID / 4));
}
__global__ void zero_out_kernel(float* __restrict__ out, int n4) {
    float4 z = make_float4(0.f, 0.f, 0.f, 0.f);
    float4* o4 = (float4*)out;
    int stride = gridDim.x * blockDim.x;
    for (int i = blockIdx.x * blockDim.x + threadIdx.x; i < n4; i += stride) o4[i] = z;
}
__global__ void zcnt_kernel() {
    if (threadIdx.x < NE) g_count[threadIdx.x] = 0;
}

__global__ void router_kernel(const float* __restrict__ x,
                              const float* __restrict__ rw,
                              const float* __restrict__ rb) {
    __shared__ float srw[NE * DIM];
    int tid = threadIdx.x;
    for (int i = tid; i < NE * DIM; i += 256) srw[i] = rw[i];
    __syncthreads();
    int warp = tid >> 5, lane = tid & 31;
    int t = blockIdx.x * 8 + warp;
    float xr[32];
#pragma unroll
    for (int i = 0; i < 32; i++) xr[i] = x[(size_t)t * DIM + i * 32 + lane];
    float lg[NE];
#pragma unroll
    for (int e = 0; e < NE; e++) {
        float s = 0.f;
#pragma unroll
        for (int i = 0; i < 32; i++) s += xr[i] * srw[e * DIM + i * 32 + lane];
#pragma unroll
        for (int o = 16; o > 0; o >>= 1) s += __shfl_xor_sync(0xffffffffu, s, o);
        lg[e] = s + rb[e];
    }
    if (lane == 0) {
        int i0 = 0;
#pragma unroll
        for (int e = 1; e < NE; e++) if (lg[e] > lg[i0]) i0 = e;
        int i1 = (i0 == 0) ? 1 : 0;
#pragma unroll
        for (int e = 0; e < NE; e++) {
            if (e == i0) continue;
            if (lg[e] > lg[i1]) i1 = e;
        }
        float e1 = __expf(lg[i1] - lg[i0]);
        g_gate[2 * t]     = 1.f / (1.f + e1);
        g_gate[2 * t + 1] = e1 / (1.f + e1);
        int pos0 = atomicAdd(&g_count[i0], 1);
        g_pairlist[i0 * PAIRS + pos0] = 2 * t;
        int pos1 = atomicAdd(&g_count[i1], 1);
        g_pairlist[i1 * PAIRS + pos1] = 2 * t + 1;
    }
}

// 2-stage mainloop (R8-proven): one barrier per K-chunk; fill(kt+1) overlaps
// compute(kt).
#define GEMM_MAINLOOP(NKC)                                                          \
    FILL(0, 0);                                                                     \
    for (int kt = 0; kt < (NKC); kt++) {                                            \
        int buf = kt & 1;                                                           \
        CP_WAIT0();                                                                 \
        __syncthreads();                                                            \
        if (kt + 1 < (NKC)) FILL(buf ^ 1, kt + 1);                                  \
        uint32_t ab = aBase + buf * ABUF, bb = bBase + buf * ABUF;                  \
        _Pragma("unroll")                                                           \
        for (int ks = 0; ks < 4; ks++) {                                            \
            uint32_t a[2][4], b[4][4];                                              \
            LDSM4(a[0], ab + ks * 32);                                              \
            LDSM4(a[1], ab + 16 * ROWB + ks * 32);                                  \
            _Pragma("unroll")                                                       \
            for (int j = 0; j < 4; j++) LDSM4(b[j], bb + j * 16 * ROWB + ks * 32);  \
            _Pragma("unroll")                                                       \
            for (int f = 0; f < 8; f++) {                                           \
                int j = f >> 1, h = f & 1;                                          \
                mma_f16(acc[0][f], a[0], b[j][h], b[j][h + 2]);                     \
                mma_f16(acc[1][f], a[1], b[j][h], b[j][h + 2]);                     \
            }                                                                       \
        }                                                                           \
    }

// ---------------- GEMM1: h = swiglu(x @ w1^T + b1)  (R8-exact) ----------------
__global__ void __launch_bounds__(256, 2) gemm1_kernel(const float* __restrict__ b1) {
    extern __shared__ __align__(1024) char sm[];
    uint32_t sb = smem_u32(sm);
    int tid = threadIdx.x;
    int m0 = 0, cnt = 0;
    int e = tile_map(blockIdx.x, m0, cnt);
    if (e < 0) return;
    int rows = min(TM, cnt - m0);
    int n0   = blockIdx.y * 64;

    int*   sp    = (int*)(sm + OFF_SP);
    float* sbias = (float*)(sm + OFF_BIAS);
    if (tid < TM) sp[tid] = (tid < rows) ? g_pairlist[e * PAIRS + m0 + tid] : -1;
    if (tid < 64) {
        sbias[tid]      = b1[(size_t)e * H2 + n0 + tid];
        sbias[64 + tid] = b1[(size_t)e * H2 + HID + n0 + tid];
    }
    __syncthreads();

    int kk = tid & 7, fr = tid >> 3;
    const __half* asrc[4]; int asz[4];
#pragma unroll
    for (int i = 0; i < 4; i++) {
        int p = sp[fr + 32 * i];
        asrc[i] = g_xb + (size_t)((p >= 0) ? (p >> 1) : 0) * DIM + kk * 8;
        asz[i]  = (p >= 0) ? 16 : 0;
    }
    const __half* wb = g_w1b + (size_t)e * H2 * DIM;
    const __half* bsrc[4];
#pragma unroll
    for (int i = 0; i < 4; i++) {
        int grow = n0 + (i >> 1) * 32 + fr + (i & 1) * HID;
        bsrc[i] = wb + (size_t)grow * DIM + kk * 8;
    }
    uint32_t adst = sb + OFF_A + fr * ROWB + kk * 16;
    uint32_t bdst = sb + OFF_B + fr * ROWB + kk * 16;

#define FILL(bufi, ktv) do {                                                   \
    uint32_t ao = (bufi) * (uint32_t)ABUF; int ks = (ktv) * KC;                \
    _Pragma("unroll") for (int i = 0; i < 4; i++)                              \
        cp16(adst + ao + i * 32 * ROWB, asrc[i] + ks, asz[i]);                 \
    _Pragma("unroll") for (int i = 0; i < 4; i++)                              \
        cp16(bdst + ao + i * 32 * ROWB, bsrc[i] + ks, 16);                     \
    CP_COMMIT(); } while (0)

    float acc[2][8][4];
#pragma unroll
    for (int mi = 0; mi < 2; mi++)
#pragma unroll
        for (int f = 0; f < 8; f++)
#pragma unroll
            for (int q = 0; q < 4; q++) acc[mi][f][q] = 0.f;

    int warp = tid >> 5, lane = tid & 31;
    int wm = warp >> 1, wn = warp & 1;
    uint32_t lrow = lane & 15, lko = (lane >> 4) * 16;
    uint32_t aBase = sb + OFF_A + (wm * 32 + lrow) * ROWB + lko;
    uint32_t bBase = sb + OFF_B + (wn * 64 + lrow) * ROWB + lko;

    GEMM_MAINLOOP(NK1)
#undef FILL

    int g = lane >> 2, tg = lane & 3;
#pragma unroll
    for (int mi = 0; mi < 2; mi++) {
        int rb = wm * 32 + mi * 16 + g;
#pragma unroll
        for (int f = 0; f < 4; f++) {
            int jj = wn * 32 + f * 8 + 2 * tg;
            float bg0 = sbias[jj],      bg1 = sbias[jj + 1];
            float bu0 = sbias[64 + jj], bu1 = sbias[64 + jj + 1];
            int j = n0 + jj;
            if (rb < rows) {
                int p = sp[rb];
                float ga = acc[mi][f][0] + bg0, ua = acc[mi][f + 4][0] + bu0;
                float gb = acc[mi][f][1] + bg1, ub = acc[mi][f + 4][1] + bu1;
                float h0 = ga / (1.f + __expf(-ga)) * ua;
                float h1 = gb / (1.f + __expf(-gb)) * ub;
                *(__half2*)&g_hbuf[(size_t)p * HID + j] = __floats2half2_rn(h0, h1);
            }
            if (rb + 8 < rows) {
                int p = sp[rb + 8];
                float ga = acc[mi][f][2] + bg0, ua = acc[mi][f + 4][2] + bu0;
                float gb = acc[mi][f][3] + bg1, ub = acc[mi][f + 4][3] + bu1;
                float h0 = ga / (1.f + __expf(-ga)) * ua;
                float h1 = gb / (1.f + __expf(-gb)) * ub;
                *(__half2*)&g_hbuf[(size_t)p * HID + j] = __floats2half2_rn(h0, h1);
            }
        }
    }
}

// ---------------- GEMM2: out += gate * (h @ w2^T + b2)  (R8-exact) ----------------
__global__ void __launch_bounds__(256, 2) gemm2_kernel(const float* __restrict__ b2,
                                                       float* __restrict__ out) {
    extern __shared__ __align__(1024) char sm[];
    uint32_t sb = smem_u32(sm);
    int tid = threadIdx.x;
    int m0 = 0, cnt = 0;
    int e = tile_map(blockIdx.x, m0, cnt);
    if (e < 0) return;
    int rows = min(TM, cnt - m0);
    int n0   = blockIdx.y * 128;

    int*   sp    = (int*)(sm + OFF_SP);
    float* sbias = (float*)(sm + OFF_BIAS);
    if (tid < TM) sp[tid] = (tid < rows) ? g_pairlist[e * PAIRS + m0 + tid] : -1;
    if (tid < 128) sbias[tid] = b2[(size_t)e * DIM + n0 + tid];
    __syncthreads();

    int kk = tid & 7, fr = tid >> 3;
    const __half* asrc[4]; int asz[4];
#pragma unroll
    for (int i = 0; i < 4; i++) {
        int p = sp[fr + 32 * i];
        asrc[i] = g_hbuf + (size_t)((p >= 0) ? p : 0) * HID + kk * 8;
        asz[i]  = (p >= 0) ? 16 : 0;
    }
    const __half* wb = g_w2b + (size_t)e * DIM * HID;
    const __half* bsrc[4];
#pragma unroll
    for (int i = 0; i < 4; i++) bsrc[i] = wb + (size_t)(n0 + fr + 32 * i) * HID + kk * 8;
    uint32_t adst = sb + OFF_A + fr * ROWB + kk * 16;
    uint32_t bdst = sb + OFF_B + fr * ROWB + kk * 16;

#define FILL(bufi, ktv) do {                                                   \
    uint32_t ao = (bufi) * (uint32_t)ABUF; int ks = (ktv) * KC;                \
    _Pragma("unroll") for (int i = 0; i < 4; i++)                              \
        cp16(adst + ao + i * 32 * ROWB, asrc[i] + ks, asz[i]);                 \
    _Pragma("unroll") for (int i = 0; i < 4; i++)                              \
        cp16(bdst + ao + i * 32 * ROWB, bsrc[i] + ks, 16);                     \
    CP_COMMIT(); } while (0)

    float acc[2][8][4];
#pragma unroll
    for (int mi = 0; mi < 2; mi++)
#pragma unroll
        for (int f = 0; f < 8; f++)
#pragma unroll
            for (int q = 0; q < 4; q++) acc[mi][f][q] = 0.f;

    int warp = tid >> 5, lane = tid & 31;
    int wm = warp >> 1, wn = warp & 1;
    uint32_t lrow = lane & 15, lko = (lane >> 4) * 16;
    uint32_t aBase = sb + OFF_A + (wm * 32 + lrow) * ROWB + lko;
    uint32_t bBase = sb + OFF_B + (wn * 64 + lrow) * ROWB + lko;

    GEMM_MAINLOOP(NK2)
#undef FILL

    int g = lane >> 2, tg = lane & 3;
#pragma unroll
    for (int mi = 0; mi < 2; mi++) {
        int rb = wm * 32 + mi * 16 + g;
#pragma unroll
        for (int f = 0; f < 8; f++) {
            int jj = wn * 64 + f * 8 + 2 * tg;
            int j = n0 + jj;
            float bb0 = sbias[jj], bb1 = sbias[jj + 1];
            if (rb < rows) {
                int p = sp[rb];
                int t = p >> 1;
                float w = g_gate[p];
                atomicAdd(&out[(size_t)t * DIM + j],     (acc[mi][f][0] + bb0) * w);
                atomicAdd(&out[(size_t)t * DIM + j + 1], (acc[mi][f][1] + bb1) * w);
            }
            if (rb + 8 < rows) {
                int p = sp[rb + 8];
                int t = p >> 1;
                float w = g_gate[p];
                atomicAdd(&out[(size_t)t * DIM + j],     (acc[mi][f][2] + bb0) * w);
                atomicAdd(&out[(size_t)t * DIM + j + 1], (acc[mi][f][3] + bb1) * w);
            }
        }
    }
}

// ---------------- launch: forked-stream schedule ----------------
// s1: cvt_x+w1   ─┐
// s2: zcnt→router ─┼→ gemm1 (main) ── gemm2 (main)
// s3: cvt_w2→zero ─────────────────┘   (overlaps gemm1)
static cudaStream_t s1, s2, s3;
static cudaEvent_t  evR, ev1, ev2, ev3;
static bool s_init = false;

extern "C" void kernel_launch(void* const* d_in, const int* in_sizes, int n_in,
                              void* d_out, int out_size) {
    const float* x  = (const float*)d_in[0];
    const float* rw = (const float*)d_in[1];
    const float* rb = (const float*)d_in[2];
    const float* w1 = (const float*)d_in[3];
    const float* b1 = (const float*)d_in[4];
    const float* w2 = (const float*)d_in[5];
    const float* b2 = (const float*)d_in[6];
    float* out = (float*)d_out;

    if (!s_init) {
        cudaStreamCreateWithFlags(&s1, cudaStreamNonBlocking);
        cudaStreamCreateWithFlags(&s2, cudaStreamNonBlocking);
        cudaStreamCreateWithFlags(&s3, cudaStreamNonBlocking);
        cudaEventCreateWithFlags(&evR, cudaEventDisableTiming);
        cudaEventCreateWithFlags(&ev1, cudaEventDisableTiming);
        cudaEventCreateWithFlags(&ev2, cudaEventDisableTiming);
        cudaEventCreateWithFlags(&ev3, cudaEventDisableTiming);
        cudaFuncSetAttribute(gemm1_kernel, cudaFuncAttributeMaxDynamicSharedMemorySize, SMEM_TOTAL);
        cudaFuncSetAttribute(gemm2_kernel, cudaFuncAttributeMaxDynamicSharedMemorySize, SMEM_TOTAL);
        s_init = true;
    }

    // fork from the (capture) stream
    cudaEventRecord(evR, 0);
    cudaStreamWaitEvent(s1, evR, 0);
    cudaStreamWaitEvent(s2, evR, 0);
    cudaStreamWaitEvent(s3, evR, 0);

    cvt_xw1_kernel<<<2048, 256, 0, s1>>>(x, w1);
    cudaEventRecord(ev1, s1);

    zcnt_kernel<<<1, 32, 0, s2>>>();
    router_kernel<<<T_TOKENS / 8, 256, 0, s2>>>(x, rw, rb);
    cudaEventRecord(ev2, s2);

    cvt_w2_kernel<<<2048, 256, 0, s3>>>(w2);
    zero_out_kernel<<<1024, 256, 0, s3>>>(out, out_size / 4);
    cudaEventRecord(ev3, s3);

    // gemm1 on main stream after xb/w1b + routing; cvt_w2/zero overlap it
    cudaStreamWaitEvent(0, ev1, 0);
    cudaStreamWaitEvent(0, ev2, 0);
    gemm1_kernel<<<dim3(MAXTILES, HID / 64), 256, SMEM_TOTAL>>>(b1);

    // gemm2 additionally needs w2b + zeroed out
    cudaStreamWaitEvent(0, ev3, 0);
    gemm2_kernel<<<dim3(MAXTILES, DIM / 128), 256, SMEM_TOTAL>>>(b2, out);
}

// round 15
// speedup vs baseline: 1.3525x; 1.0754x over previous
#include <cuda_runtime.h>
#include <cuda_fp16.h>
#include <cstdint>

#define T_TOKENS 8192
#define DIM      1024
#define HID      4096
#define H2       8192
#define NE       8
#define PAIRS    16384
#define TM       128
#define KC       64              // K halves per chunk (128B row)
#define ROWB     144             // padded row stride (conflict-free ldmatrix)
#define MAXTILES 136
#define NK1      (DIM/KC)        // 16
#define NK2      (HID/KC)        // 64

// dynamic smem layout (per CTA) — 2-stage (R8-proven)
#define OFF_SP   0
#define OFF_BIAS 512
#define OFF_A    2048
#define ABUF     (128*ROWB)      // 18432 per stage
#define OFF_B    (OFF_A + 2*ABUF)
#define SMEM_TOTAL (OFF_B + 2*ABUF)   // 75776

// ---------------- device scratch ----------------
__device__ float  g_gate[PAIRS];
__device__ int    g_pairlist[NE * PAIRS];
__device__ int    g_count[NE];
__device__ __half g_xb[T_TOKENS * DIM];
__device__ __half g_w1b[(size_t)NE * H2 * DIM];
__device__ __half g_w2b[(size_t)NE * DIM * HID];
__device__ __half g_hbuf[(size_t)PAIRS * HID];

// ---------------- helpers ----------------
__device__ __forceinline__ uint32_t smem_u32(const void* p) {
    return (uint32_t)__cvta_generic_to_shared(p);
}
__device__ __forceinline__ void cp16(uint32_t dst, const void* src, int sz) {
    asm volatile("cp.async.cg.shared.global [%0], [%1], 16, %2;\n" :: "r"(dst), "l"(src), "r"(sz));
}
#define CP_COMMIT() asm volatile("cp.async.commit_group;\n")
#define CP_WAIT0()  asm volatile("cp.async.wait_group 0;\n")

#define LDSM4(r, addr) \
    asm volatile("ldmatrix.sync.aligned.m8n8.x4.shared.b16 {%0,%1,%2,%3}, [%4];" \
        : "=r"((r)[0]), "=r"((r)[1]), "=r"((r)[2]), "=r"((r)[3]) : "r"(addr))

__device__ __forceinline__ void mma_f16(float c[4], const uint32_t a[4],
                                        uint32_t b0, uint32_t b1) {
    asm volatile(
        "mma.sync.aligned.m16n8k16.row.col.f32.f16.f16.f32 "
        "{%0,%1,%2,%3}, {%4,%5,%6,%7}, {%8,%9}, {%0,%1,%2,%3};\n"
        : "+f"(c[0]), "+f"(c[1]), "+f"(c[2]), "+f"(c[3])
        : "r"(a[0]), "r"(a[1]), "r"(a[2]), "r"(a[3]), "r"(b0), "r"(b1));
}

// map m-tile index -> (expert, m0); returns expert or -1
__device__ __forceinline__ int tile_map(int bx, int& m0, int& cnt) {
    int off = 0, e = -1;
#pragma unroll
    for (int i = 0; i < NE; i++) {
        int c = g_count[i];
        int t = (c + TM - 1) / TM;
        if (e < 0 && bx < off + t) { e = i; m0 = (bx - off) * TM; cnt = c; }
        off += t;
    }
    return e;
}

// ---------------- converts / zero / router ----------------
__device__ __forceinline__ void f2h_body(const float4* __restrict__ src,
                                         float2* __restrict__ dst, int n4) {
    int stride = gridDim.x * blockDim.x;
    for (int i = blockIdx.x * blockDim.x + threadIdx.x; i < n4; i += stride) {
        float4 v = src[i];
        union { __half2 h2[2]; float2 f; } u;
        u.h2[0] = __float22half2_rn(make_float2(v.x, v.y));
        u.h2[1] = __float22half2_rn(make_float2(v.z, v.w));
        dst[i] = u.f;
    }
}
__global__ void cvt_xw1_kernel(const float* __restrict__ x,
                               const float* __restrict__ w1) {
    f2h_body((const float4*)x,  (float2*)g_xb,  T_TOKENS * DIM / 4);
    f2h_body((const float4*)w1, (float2*)g_w1b, (int)((size_t)NE * H2 * DIM / 4));
}
__global__ void cvt_w2_kernel(const float* __restrict__ w2) {
    f2h_body((const float4*)w2, (float2*)g_w2b, (int)((size_t)NE * DIM * HID / 4));
}
__global__ void zero_out_kernel(float* __restrict__ out, int n4) {
    float4 z = make_float4(0.f, 0.f, 0.f, 0.f);
    float4* o4 = (float4*)out;
    int stride = gridDim.x * blockDim.x;
    for (int i = blockIdx.x * blockDim.x + threadIdx.x; i < n4; i += stride) o4[i] = z;
}
__global__ void zcnt_kernel() {
    if (threadIdx.x < NE) g_count[threadIdx.x] = 0;
}

__global__ void router_kernel(const float* __restrict__ x,
                              const float* __restrict__ rw,
                              const float* __restrict__ rb) {
    __shared__ float srw[NE * DIM];
    int tid = threadIdx.x;
    for (int i = tid; i < NE * DIM; i += 256) srw[i] = rw[i];
    __syncthreads();
    int warp = tid >> 5, lane = tid & 31;
    int t = blockIdx.x * 8 + warp;
    float xr[32];
#pragma unroll
    for (int i = 0; i < 32; i++) xr[i] = x[(size_t)t * DIM + i * 32 + lane];
    float lg[NE];
#pragma unroll
    for (int e = 0; e < NE; e++) {
        float s = 0.f;
#pragma unroll
        for (int i = 0; i < 32; i++) s += xr[i] * srw[e * DIM + i * 32 + lane];
#pragma unroll
        for (int o = 16; o > 0; o >>= 1) s += __shfl_xor_sync(0xffffffffu, s, o);
        lg[e] = s + rb[e];
    }
    if (lane == 0) {
        int i0 = 0;
#pragma unroll
        for (int e = 1; e < NE; e++) if (lg[e] > lg[i0]) i0 = e;
        int i1 = (i0 == 0) ? 1 : 0;
#pragma unroll
        for (int e = 0; e < NE; e++) {
            if (e == i0) continue;
            if (lg[e] > lg[i1]) i1 = e;
        }
        float e1 = __expf(lg[i1] - lg[i0]);
        g_gate[2 * t]     = 1.f / (1.f + e1);
        g_gate[2 * t + 1] = e1 / (1.f + e1);
        int pos0 = atomicAdd(&g_count[i0], 1);
        g_pairlist[i0 * PAIRS + pos0] = 2 * t;
        int pos1 = atomicAdd(&g_count[i1], 1);
        g_pairlist[i1 * PAIRS + pos1] = 2 * t + 1;
    }
}

// 2-stage mainloop with FILL software-pipelined into the ks blocks:
// part ks of the next chunk's fill (1 A + 1 B cp.async per thread) is issued at
// the top of ks block, interleaving LSU pressure with HMMA work instead of
// convoying all 8 cp.asyncs at the barrier. One commit per chunk after the
// last part; CP_WAIT0 one iteration later gives the group a full chunk to land.
#define GEMM_MAINLOOP(NKC)                                                          \
    FILLPART(0, 0, 0); FILLPART(0, 0, 1); FILLPART(0, 0, 2); FILLPART(0, 0, 3);     \
    CP_COMMIT();                                                                    \
    for (int kt = 0; kt < (NKC); kt++) {                                            \
        int buf = kt & 1;                                                           \
        CP_WAIT0();                                                                 \
        __syncthreads();                                                            \
        bool pref = (kt + 1 < (NKC));                                               \
        uint32_t ab = aBase + buf * ABUF, bb = bBase + buf * ABUF;                  \
        _Pragma("unroll")                                                           \
        for (int ks = 0; ks < 4; ks++) {                                            \
            if (pref) FILLPART(buf ^ 1, kt + 1, ks);                                \
            uint32_t a[2][4], b[4][4];                                              \
            LDSM4(a[0], ab + ks * 32);                                              \
            LDSM4(a[1], ab + 16 * ROWB + ks * 32);                                  \
            _Pragma("unroll")                                                       \
            for (int j = 0; j < 4; j++) LDSM4(b[j], bb + j * 16 * ROWB + ks * 32);  \
            _Pragma("unroll")                                                       \
            for (int f = 0; f < 8; f++) {                                           \
                int j = f >> 1, h = f & 1;                                          \
                mma_f16(acc[0][f], a[0], b[j][h], b[j][h + 2]);                     \
                mma_f16(acc[1][f], a[1], b[j][h], b[j][h + 2]);                     \
            }                                                                       \
        }                                                                           \
        if (pref) CP_COMMIT();                                                      \
    }

// ---------------- GEMM1: h = swiglu(x @ w1^T + b1) ----------------
__global__ void __launch_bounds__(256, 2) gemm1_kernel(const float* __restrict__ b1) {
    extern __shared__ __align__(1024) char sm[];
    uint32_t sb = smem_u32(sm);
    int tid = threadIdx.x;
    int m0 = 0, cnt = 0;
    int e = tile_map(blockIdx.x, m0, cnt);
    if (e < 0) return;
    int rows = min(TM, cnt - m0);
    int n0   = blockIdx.y * 64;

    int*   sp    = (int*)(sm + OFF_SP);
    float* sbias = (float*)(sm + OFF_BIAS);
    if (tid < TM) sp[tid] = (tid < rows) ? g_pairlist[e * PAIRS + m0 + tid] : -1;
    if (tid < 64) {
        sbias[tid]      = b1[(size_t)e * H2 + n0 + tid];
        sbias[64 + tid] = b1[(size_t)e * H2 + HID + n0 + tid];
    }
    __syncthreads();

    int kk = tid & 7, fr = tid >> 3;
    const __half* asrc[4]; int asz[4];
#pragma unroll
    for (int i = 0; i < 4; i++) {
        int p = sp[fr + 32 * i];
        asrc[i] = g_xb + (size_t)((p >= 0) ? (p >> 1) : 0) * DIM + kk * 8;
        asz[i]  = (p >= 0) ? 16 : 0;
    }
    const __half* wb = g_w1b + (size_t)e * H2 * DIM;
    const __half* bsrc[4];
#pragma unroll
    for (int i = 0; i < 4; i++) {
        int grow = n0 + (i >> 1) * 32 + fr + (i & 1) * HID;
        bsrc[i] = wb + (size_t)grow * DIM + kk * 8;
    }
    uint32_t adst = sb + OFF_A + fr * ROWB + kk * 16;
    uint32_t bdst = sb + OFF_B + fr * ROWB + kk * 16;

#define FILLPART(bufi, ktv, p) do {                                            \
    uint32_t ao = (bufi) * (uint32_t)ABUF; int ks_ = (ktv) * KC;               \
    cp16(adst + ao + (p) * 32 * ROWB, asrc[p] + ks_, asz[p]);                  \
    cp16(bdst + ao + (p) * 32 * ROWB, bsrc[p] + ks_, 16);                      \
    } while (0)

    float acc[2][8][4];
#pragma unroll
    for (int mi = 0; mi < 2; mi++)
#pragma unroll
        for (int f = 0; f < 8; f++)
#pragma unroll
            for (int q = 0; q < 4; q++) acc[mi][f][q] = 0.f;

    int warp = tid >> 5, lane = tid & 31;
    int wm = warp >> 1, wn = warp & 1;
    uint32_t lrow = lane & 15, lko = (lane >> 4) * 16;
    uint32_t aBase = sb + OFF_A + (wm * 32 + lrow) * ROWB + lko;
    uint32_t bBase = sb + OFF_B + (wn * 64 + lrow) * ROWB + lko;

    GEMM_MAINLOOP(NK1)
#undef FILLPART

    int g = lane >> 2, tg = lane & 3;
#pragma unroll
    for (int mi = 0; mi < 2; mi++) {
        int rb = wm * 32 + mi * 16 + g;
#pragma unroll
        for (int f = 0; f < 4; f++) {
            int jj = wn * 32 + f * 8 + 2 * tg;
            float bg0 = sbias[jj],      bg1 = sbias[jj + 1];
            float bu0 = sbias[64 + jj], bu1 = sbias[64 + jj + 1];
            int j = n0 + jj;
            if (rb < rows) {
                int p = sp[rb];
                float ga = acc[mi][f][0] + bg0, ua = acc[mi][f + 4][0] + bu0;
                float gb = acc[mi][f][1] + bg1, ub = acc[mi][f + 4][1] + bu1;
                float h0 = ga / (1.f + __expf(-ga)) * ua;
                float h1 = gb / (1.f + __expf(-gb)) * ub;
                *(__half2*)&g_hbuf[(size_t)p * HID + j] = __floats2half2_rn(h0, h1);
            }
            if (rb + 8 < rows) {
                int p = sp[rb + 8];
                float ga = acc[mi][f][2] + bg0, ua = acc[mi][f + 4][2] + bu0;
                float gb = acc[mi][f][3] + bg1, ub = acc[mi][f + 4][3] + bu1;
                float h0 = ga / (1.f + __expf(-ga)) * ua;
                float h1 = gb / (1.f + __expf(-gb)) * ub;
                *(__half2*)&g_hbuf[(size_t)p * HID + j] = __floats2half2_rn(h0, h1);
            }
        }
    }
}

// ---------------- GEMM2: out += gate * (h @ w2^T + b2) ----------------
__global__ void __launch_bounds__(256, 2) gemm2_kernel(const float* __restrict__ b2,
                                                       float* __restrict__ out) {
    extern __shared__ __align__(1024) char sm[];
    uint32_t sb = smem_u32(sm);
    int tid = threadIdx.x;
    int m0 = 0, cnt = 0;
    int e = tile_map(blockIdx.x, m0, cnt);
    if (e < 0) return;
    int rows = min(TM, cnt - m0);
    int n0   = blockIdx.y * 128;

    int*   sp    = (int*)(sm + OFF_SP);
    float* sbias = (float*)(sm + OFF_BIAS);
    if (tid < TM) sp[tid] = (tid < rows) ? g_pairlist[e * PAIRS + m0 + tid] : -1;
    if (tid < 128) sbias[tid] = b2[(size_t)e * DIM + n0 + tid];
    __syncthreads();

    int kk = tid & 7, fr = tid >> 3;
    const __half* asrc[4]; int asz[4];
#pragma unroll
    for (int i = 0; i < 4; i++) {
        int p = sp[fr + 32 * i];
        asrc[i] = g_hbuf + (size_t)((p >= 0) ? p : 0) * HID + kk * 8;
        asz[i]  = (p >= 0) ? 16 : 0;
    }
    const __half* wb = g_w2b + (size_t)e * DIM * HID;
    const __half* bsrc[4];
#pragma unroll
    for (int i = 0; i < 4; i++) bsrc[i] = wb + (size_t)(n0 + fr + 32 * i) * HID + kk * 8;
    uint32_t adst = sb + OFF_A + fr * ROWB + kk * 16;
    uint32_t bdst = sb + OFF_B + fr * ROWB + kk * 16;

#define FILLPART(bufi, ktv, p) do {                                            \
    uint32_t ao = (bufi) * (uint32_t)ABUF; int ks_ = (ktv) * KC;               \
    cp16(adst + ao + (p) * 32 * ROWB, asrc[p] + ks_, asz[p]);                  \
    cp16(bdst + ao + (p) * 32 * ROWB, bsrc[p] + ks_, 16);                      \
    } while (0)

    float acc[2][8][4];
#pragma unroll
    for (int mi = 0; mi < 2; mi++)
#pragma unroll
        for (int f = 0; f < 8; f++)
#pragma unroll
            for (int q = 0; q < 4; q++) acc[mi][f][q] = 0.f;

    int warp = tid >> 5, lane = tid & 31;
    int wm = warp >> 1, wn = warp & 1;
    uint32_t lrow = lane & 15, lko = (lane >> 4) * 16;
    uint32_t aBase = sb + OFF_A + (wm * 32 + lrow) * ROWB + lko;
    uint32_t bBase = sb + OFF_B + (wn * 64 + lrow) * ROWB + lko;

    GEMM_MAINLOOP(NK2)
#undef FILLPART

    int g = lane >> 2, tg = lane & 3;
#pragma unroll
    for (int mi = 0; mi < 2; mi++) {
        int rb = wm * 32 + mi * 16 + g;
#pragma unroll
        for (int f = 0; f < 8; f++) {
            int jj = wn * 64 + f * 8 + 2 * tg;
            int j = n0 + jj;
            float bb0 = sbias[jj], bb1 = sbias[jj + 1];
            if (rb < rows) {
                int p = sp[rb];
                int t = p >> 1;
                float w = g_gate[p];
                atomicAdd(&out[(size_t)t * DIM + j],     (acc[mi][f][0] + bb0) * w);
                atomicAdd(&out[(size_t)t * DIM + j + 1], (acc[mi][f][1] + bb1) * w);
            }
            if (rb + 8 < rows) {
                int p = sp[rb + 8];
                int t = p >> 1;
                float w = g_gate[p];
                atomicAdd(&out[(size_t)t * DIM + j],     (acc[mi][f][2] + bb0) * w);
                atomicAdd(&out[(size_t)t * DIM + j + 1], (acc[mi][f][3] + bb1) * w);
            }
        }
    }
}

// ---------------- launch: forked-stream schedule (R14-proven) ----------------
static cudaStream_t s1, s2, s3;
static cudaEvent_t  evR, ev1, ev2, ev3;
static bool s_init = false;

extern "C" void kernel_launch(void* const* d_in, const int* in_sizes, int n_in,
                              void* d_out, int out_size) {
    const float* x  = (const float*)d_in[0];
    const float* rw = (const float*)d_in[1];
    const float* rb = (const float*)d_in[2];
    const float* w1 = (const float*)d_in[3];
    const float* b1 = (const float*)d_in[4];
    const float* w2 = (const float*)d_in[5];
    const float* b2 = (const float*)d_in[6];
    float* out = (float*)d_out;

    if (!s_init) {
        cudaStreamCreateWithFlags(&s1, cudaStreamNonBlocking);
        cudaStreamCreateWithFlags(&s2, cudaStreamNonBlocking);
        cudaStreamCreateWithFlags(&s3, cudaStreamNonBlocking);
        cudaEventCreateWithFlags(&evR, cudaEventDisableTiming);
        cudaEventCreateWithFlags(&ev1, cudaEventDisableTiming);
        cudaEventCreateWithFlags(&ev2, cudaEventDisableTiming);
        cudaEventCreateWithFlags(&ev3, cudaEventDisableTiming);
        cudaFuncSetAttribute(gemm1_kernel, cudaFuncAttributeMaxDynamicSharedMemorySize, SMEM_TOTAL);
        cudaFuncSetAttribute(gemm2_kernel, cudaFuncAttributeMaxDynamicSharedMemorySize, SMEM_TOTAL);
        s_init = true;
    }

    cudaEventRecord(evR, 0);
    cudaStreamWaitEvent(s1, evR, 0);
    cudaStreamWaitEvent(s2, evR, 0);
    cudaStreamWaitEvent(s3, evR, 0);

    cvt_xw1_kernel<<<2048, 256, 0, s1>>>(x, w1);
    cudaEventRecord(ev1, s1);

    zcnt_kernel<<<1, 32, 0, s2>>>();
    router_kernel<<<T_TOKENS / 8, 256, 0, s2>>>(x, rw, rb);
    cudaEventRecord(ev2, s2);

    cvt_w2_kernel<<<2048, 256, 0, s3>>>(w2);
    zero_out_kernel<<<1024, 256, 0, s3>>>(out, out_size / 4);
    cudaEventRecord(ev3, s3);

    cudaStreamWaitEvent(0, ev1, 0);
    cudaStreamWaitEvent(0, ev2, 0);
    gemm1_kernel<<<dim3(MAXTILES, HID / 64), 256, SMEM_TOTAL>>>(b1);

    cudaStreamWaitEvent(0, ev3, 0);
    gemm2_kernel<<<dim3(MAXTILES, DIM / 128), 256, SMEM_TOTAL>>>(b2, out);
}

// round 16
// speedup vs baseline: 1.4381x; 1.0633x over previous
#include <cuda_runtime.h>
#include <cuda_fp16.h>
#include <cstdint>

#define T_TOKENS 8192
#define DIM      1024
#define HID      4096
#define H2       8192
#define NE       8
#define PAIRS    16384
#define TM       128
#define KC       64              // K halves per chunk (128B row)
#define ROWB     144             // padded row stride (conflict-free ldmatrix)
#define MAXTILES 136
#define NK1      (DIM/KC)        // 16
#define NK2      (HID/KC)        // 64
#define NSTG     3               // pipeline stages (R16: slack for the fill tail)

// dynamic smem layout (per CTA) — 3-stage, 2 CTA/SM
#define OFF_SP   0
#define OFF_BIAS 512
#define OFF_A    2048
#define ABUF     (128*ROWB)      // 18432 per stage
#define OFF_B    (OFF_A + NSTG*ABUF)
#define SMEM_TOTAL (OFF_B + NSTG*ABUF)   // 112640

// ---------------- device scratch ----------------
__device__ float  g_gate[PAIRS];
__device__ int    g_pairlist[NE * PAIRS];
__device__ int    g_count[NE];
__device__ __half g_xb[T_TOKENS * DIM];
__device__ __half g_w1b[(size_t)NE * H2 * DIM];
__device__ __half g_w2b[(size_t)NE * DIM * HID];
__device__ __half g_hbuf[(size_t)PAIRS * HID];

// ---------------- helpers ----------------
__device__ __forceinline__ uint32_t smem_u32(const void* p) {
    return (uint32_t)__cvta_generic_to_shared(p);
}
__device__ __forceinline__ void cp16(uint32_t dst, const void* src, int sz) {
    asm volatile("cp.async.cg.shared.global [%0], [%1], 16, %2;\n" :: "r"(dst), "l"(src), "r"(sz));
}
#define CP_COMMIT() asm volatile("cp.async.commit_group;\n")
#define CP_WAIT1()  asm volatile("cp.async.wait_group 1;\n")
#define CP_WAIT0()  asm volatile("cp.async.wait_group 0;\n")

#define LDSM4(r, addr) \
    asm volatile("ldmatrix.sync.aligned.m8n8.x4.shared.b16 {%0,%1,%2,%3}, [%4];" \
        : "=r"((r)[0]), "=r"((r)[1]), "=r"((r)[2]), "=r"((r)[3]) : "r"(addr))

__device__ __forceinline__ void mma_f16(float c[4], const uint32_t a[4],
                                        uint32_t b0, uint32_t b1) {
    asm volatile(
        "mma.sync.aligned.m16n8k16.row.col.f32.f16.f16.f32 "
        "{%0,%1,%2,%3}, {%4,%5,%6,%7}, {%8,%9}, {%0,%1,%2,%3};\n"
        : "+f"(c[0]), "+f"(c[1]), "+f"(c[2]), "+f"(c[3])
        : "r"(a[0]), "r"(a[1]), "r"(a[2]), "r"(a[3]), "r"(b0), "r"(b1));
}

// map m-tile index -> (expert, m0); returns expert or -1
__device__ __forceinline__ int tile_map(int bx, int& m0, int& cnt) {
    int off = 0, e = -1;
#pragma unroll
    for (int i = 0; i < NE; i++) {
        int c = g_count[i];
        int t = (c + TM - 1) / TM;
        if (e < 0 && bx < off + t) { e = i; m0 = (bx - off) * TM; cnt = c; }
        off += t;
    }
    return e;
}

// ---------------- converts / zero / router ----------------
__device__ __forceinline__ void f2h_body(const float4* __restrict__ src,
                                         float2* __restrict__ dst, int n4) {
    int stride = gridDim.x * blockDim.x;
    for (int i = blockIdx.x * blockDim.x + threadIdx.x; i < n4; i += stride) {
        float4 v = src[i];
        union { __half2 h2[2]; float2 f; } u;
        u.h2[0] = __float22half2_rn(make_float2(v.x, v.y));
        u.h2[1] = __float22half2_rn(make_float2(v.z, v.w));
        dst[i] = u.f;
    }
}
__global__ void cvt_xw1_kernel(const float* __restrict__ x,
                               const float* __restrict__ w1) {
    f2h_body((const float4*)x,  (float2*)g_xb,  T_TOKENS * DIM / 4);
    f2h_body((const float4*)w1, (float2*)g_w1b, (int)((size_t)NE * H2 * DIM / 4));
}
__global__ void cvt_w2_kernel(const float* __restrict__ w2) {
    f2h_body((const float4*)w2, (float2*)g_w2b, (int)((size_t)NE * DIM * HID / 4));
}
__global__ void zero_out_kernel(float* __restrict__ out, int n4) {
    float4 z = make_float4(0.f, 0.f, 0.f, 0.f);
    float4* o4 = (float4*)out;
    int stride = gridDim.x * blockDim.x;
    for (int i = blockIdx.x * blockDim.x + threadIdx.x; i < n4; i += stride) o4[i] = z;
}
__global__ void zcnt_kernel() {
    if (threadIdx.x < NE) g_count[threadIdx.x] = 0;
}

__global__ void router_kernel(const float* __restrict__ x,
                              const float* __restrict__ rw,
                              const float* __restrict__ rb) {
    __shared__ float srw[NE * DIM];
    int tid = threadIdx.x;
    for (int i = tid; i < NE * DIM; i += 256) srw[i] = rw[i];
    __syncthreads();
    int warp = tid >> 5, lane = tid & 31;
    int t = blockIdx.x * 8 + warp;
    float xr[32];
#pragma unroll
    for (int i = 0; i < 32; i++) xr[i] = x[(size_t)t * DIM + i * 32 + lane];
    float lg[NE];
#pragma unroll
    for (int e = 0; e < NE; e++) {
        float s = 0.f;
#pragma unroll
        for (int i = 0; i < 32; i++) s += xr[i] * srw[e * DIM + i * 32 + lane];
#pragma unroll
        for (int o = 16; o > 0; o >>= 1) s += __shfl_xor_sync(0xffffffffu, s, o);
        lg[e] = s + rb[e];
    }
    if (lane == 0) {
        int i0 = 0;
#pragma unroll
        for (int e = 1; e < NE; e++) if (lg[e] > lg[i0]) i0 = e;
        int i1 = (i0 == 0) ? 1 : 0;
#pragma unroll
        for (int e = 0; e < NE; e++) {
            if (e == i0) continue;
            if (lg[e] > lg[i1]) i1 = e;
        }
        float e1 = __expf(lg[i1] - lg[i0]);
        g_gate[2 * t]     = 1.f / (1.f + e1);
        g_gate[2 * t + 1] = e1 / (1.f + e1);
        int pos0 = atomicAdd(&g_count[i0], 1);
        g_pairlist[i0 * PAIRS + pos0] = 2 * t;
        int pos1 = atomicAdd(&g_count[i1], 1);
        g_pairlist[i1 * PAIRS + pos1] = 2 * t + 1;
    }
}

// 3-stage mainloop with FILL software-pipelined into the ks blocks (R15) plus
// a full chunk of slack for the fill tail (horizon kt+2): a part issued during
// chunk kt is waited on only at the start of chunk kt+2. wait_group 1 drains
// fill(kt) while leaving fill(kt+1) in flight. Buffer (kt+2)%3 was last
// computed at chunk kt-1, ordered by this iteration's barrier.
#define GEMM_MAINLOOP(NKC)                                                          \
    FILLPART(0, 0, 0); FILLPART(0, 0, 1); FILLPART(0, 0, 2); FILLPART(0, 0, 3);     \
    CP_COMMIT();                                                                    \
    FILLPART(1, 1, 0); FILLPART(1, 1, 1); FILLPART(1, 1, 2); FILLPART(1, 1, 3);     \
    CP_COMMIT();                                                                    \
    for (int kt = 0; kt < (NKC); kt++) {                                            \
        int buf = kt % NSTG;                                                        \
        if (kt + 1 < (NKC)) CP_WAIT1(); else CP_WAIT0();                            \
        __syncthreads();                                                            \
        bool pref = (kt + 2 < (NKC));                                               \
        int nb = (kt + 2) % NSTG;                                                   \
        uint32_t ab = aBase + buf * ABUF, bb = bBase + buf * ABUF;                  \
        _Pragma("unroll")                                                           \
        for (int ks = 0; ks < 4; ks++) {                                            \
            if (pref) FILLPART(nb, kt + 2, ks);                                     \
            uint32_t a[2][4], b[4][4];                                              \
            LDSM4(a[0], ab + ks * 32);                                              \
            LDSM4(a[1], ab + 16 * ROWB + ks * 32);                                  \
            _Pragma("unroll")                                                       \
            for (int j = 0; j < 4; j++) LDSM4(b[j], bb + j * 16 * ROWB + ks * 32);  \
            _Pragma("unroll")                                                       \
            for (int f = 0; f < 8; f++) {                                           \
                int j = f >> 1, h = f & 1;                                          \
                mma_f16(acc[0][f], a[0], b[j][h], b[j][h + 2]);                     \
                mma_f16(acc[1][f], a[1], b[j][h], b[j][h + 2]);                     \
            }                                                                       \
        }                                                                           \
        if (pref) CP_COMMIT();                                                      \
    }

// ---------------- GEMM1: h = swiglu(x @ w1^T + b1) ----------------
__global__ void __launch_bounds__(256, 2) gemm1_kernel(const float* __restrict__ b1) {
    extern __shared__ __align__(1024) char sm[];
    uint32_t sb = smem_u32(sm);
    int tid = threadIdx.x;
    int m0 = 0, cnt = 0;
    int e = tile_map(blockIdx.x, m0, cnt);
    if (e < 0) return;
    int rows = min(TM, cnt - m0);
    int n0   = blockIdx.y * 64;

    int*   sp    = (int*)(sm + OFF_SP);
    float* sbias = (float*)(sm + OFF_BIAS);
    if (tid < TM) sp[tid] = (tid < rows) ? g_pairlist[e * PAIRS + m0 + tid] : -1;
    if (tid < 64) {
        sbias[tid]      = b1[(size_t)e * H2 + n0 + tid];
        sbias[64 + tid] = b1[(size_t)e * H2 + HID + n0 + tid];
    }
    __syncthreads();

    int kk = tid & 7, fr = tid >> 3;
    const __half* asrc[4]; int asz[4];
#pragma unroll
    for (int i = 0; i < 4; i++) {
        int p = sp[fr + 32 * i];
        asrc[i] = g_xb + (size_t)((p >= 0) ? (p >> 1) : 0) * DIM + kk * 8;
        asz[i]  = (p >= 0) ? 16 : 0;
    }
    const __half* wb = g_w1b + (size_t)e * H2 * DIM;
    const __half* bsrc[4];
#pragma unroll
    for (int i = 0; i < 4; i++) {
        int grow = n0 + (i >> 1) * 32 + fr + (i & 1) * HID;
        bsrc[i] = wb + (size_t)grow * DIM + kk * 8;
    }
    uint32_t adst = sb + OFF_A + fr * ROWB + kk * 16;
    uint32_t bdst = sb + OFF_B + fr * ROWB + kk * 16;

#define FILLPART(bufi, ktv, p) do {                                            \
    uint32_t ao = (bufi) * (uint32_t)ABUF; int ks_ = (ktv) * KC;               \
    cp16(adst + ao + (p) * 32 * ROWB, asrc[p] + ks_, asz[p]);                  \
    cp16(bdst + ao + (p) * 32 * ROWB, bsrc[p] + ks_, 16);                      \
    } while (0)

    float acc[2][8][4];
#pragma unroll
    for (int mi = 0; mi < 2; mi++)
#pragma unroll
        for (int f = 0; f < 8; f++)
#pragma unroll
            for (int q = 0; q < 4; q++) acc[mi][f][q] = 0.f;

    int warp = tid >> 5, lane = tid & 31;
    int wm = warp >> 1, wn = warp & 1;
    uint32_t lrow = lane & 15, lko = (lane >> 4) * 16;
    uint32_t aBase = sb + OFF_A + (wm * 32 + lrow) * ROWB + lko;
    uint32_t bBase = sb + OFF_B + (wn * 64 + lrow) * ROWB + lko;

    GEMM_MAINLOOP(NK1)
#undef FILLPART

    int g = lane >> 2, tg = lane & 3;
#pragma unroll
    for (int mi = 0; mi < 2; mi++) {
        int rb = wm * 32 + mi * 16 + g;
#pragma unroll
        for (int f = 0; f < 4; f++) {
            int jj = wn * 32 + f * 8 + 2 * tg;
            float bg0 = sbias[jj],      bg1 = sbias[jj + 1];
            float bu0 = sbias[64 + jj], bu1 = sbias[64 + jj + 1];
            int j = n0 + jj;
            if (rb < rows) {
                int p = sp[rb];
                float ga = acc[mi][f][0] + bg0, ua = acc[mi][f + 4][0] + bu0;
                float gb = acc[mi][f][1] + bg1, ub = acc[mi][f + 4][1] + bu1;
                float h0 = ga / (1.f + __expf(-ga)) * ua;
                float h1 = gb / (1.f + __expf(-gb)) * ub;
                *(__half2*)&g_hbuf[(size_t)p * HID + j] = __floats2half2_rn(h0, h1);
            }
            if (rb + 8 < rows) {
                int p = sp[rb + 8];
                float ga = acc[mi][f][2] + bg0, ua = acc[mi][f + 4][2] + bu0;
                float gb = acc[mi][f][3] + bg1, ub = acc[mi][f + 4][3] + bu1;
                float h0 = ga / (1.f + __expf(-ga)) * ua;
                float h1 = gb / (1.f + __expf(-gb)) * ub;
                *(__half2*)&g_hbuf[(size_t)p * HID + j] = __floats2half2_rn(h0, h1);
            }
        }
    }
}

// ---------------- GEMM2: out += gate * (h @ w2^T + b2) ----------------
__global__ void __launch_bounds__(256, 2) gemm2_kernel(const float* __restrict__ b2,
                                                       float* __restrict__ out) {
    extern __shared__ __align__(1024) char sm[];
    uint32_t sb = smem_u32(sm);
    int tid = threadIdx.x;
    int m0 = 0, cnt = 0;
    int e = tile_map(blockIdx.x, m0, cnt);
    if (e < 0) return;
    int rows = min(TM, cnt - m0);
    int n0   = blockIdx.y * 128;

    int*   sp    = (int*)(sm + OFF_SP);
    float* sbias = (float*)(sm + OFF_BIAS);
    if (tid < TM) sp[tid] = (tid < rows) ? g_pairlist[e * PAIRS + m0 + tid] : -1;
    if (tid < 128) sbias[tid] = b2[(size_t)e * DIM + n0 + tid];
    __syncthreads();

    int kk = tid & 7, fr = tid >> 3;
    const __half* asrc[4]; int asz[4];
#pragma unroll
    for (int i = 0; i < 4; i++) {
        int p = sp[fr + 32 * i];
        asrc[i] = g_hbuf + (size_t)((p >= 0) ? p : 0) * HID + kk * 8;
        asz[i]  = (p >= 0) ? 16 : 0;
    }
    const __half* wb = g_w2b + (size_t)e * DIM * HID;
    const __half* bsrc[4];
#pragma unroll
    for (int i = 0; i < 4; i++) bsrc[i] = wb + (size_t)(n0 + fr + 32 * i) * HID + kk * 8;
    uint32_t adst = sb + OFF_A + fr * ROWB + kk * 16;
    uint32_t bdst = sb + OFF_B + fr * ROWB + kk * 16;

#define FILLPART(bufi, ktv, p) do {                                            \
    uint32_t ao = (bufi) * (uint32_t)ABUF; int ks_ = (ktv) * KC;               \
    cp16(adst + ao + (p) * 32 * ROWB, asrc[p] + ks_, asz[p]);                  \
    cp16(bdst + ao + (p) * 32 * ROWB, bsrc[p] + ks_, 16);                      \
    } while (0)

    float acc[2][8][4];
#pragma unroll
    for (int mi = 0; mi < 2; mi++)
#pragma unroll
        for (int f = 0; f < 8; f++)
#pragma unroll
            for (int q = 0; q < 4; q++) acc[mi][f][q] = 0.f;

    int warp = tid >> 5, lane = tid & 31;
    int wm = warp >> 1, wn = warp & 1;
    uint32_t lrow = lane & 15, lko = (lane >> 4) * 16;
    uint32_t aBase = sb + OFF_A + (wm * 32 + lrow) * ROWB + lko;
    uint32_t bBase = sb + OFF_B + (wn * 64 + lrow) * ROWB + lko;

    GEMM_MAINLOOP(NK2)
#undef FILLPART

    int g = lane >> 2, tg = lane & 3;
#pragma unroll
    for (int mi = 0; mi < 2; mi++) {
        int rb = wm * 32 + mi * 16 + g;
#pragma unroll
        for (int f = 0; f < 8; f++) {
            int jj = wn * 64 + f * 8 + 2 * tg;
            int j = n0 + jj;
            float bb0 = sbias[jj], bb1 = sbias[jj + 1];
            if (rb < rows) {
                int p = sp[rb];
                int t = p >> 1;
                float w = g_gate[p];
                atomicAdd(&out[(size_t)t * DIM + j],     (acc[mi][f][0] + bb0) * w);
                atomicAdd(&out[(size_t)t * DIM + j + 1], (acc[mi][f][1] + bb1) * w);
            }
            if (rb + 8 < rows) {
                int p = sp[rb + 8];
                int t = p >> 1;
                float w = g_gate[p];
                atomicAdd(&out[(size_t)t * DIM + j],     (acc[mi][f][2] + bb0) * w);
                atomicAdd(&out[(size_t)t * DIM + j + 1], (acc[mi][f][3] + bb1) * w);
            }
        }
    }
}

// ---------------- launch: forked-stream schedule (R14-proven) ----------------
static cudaStream_t s1, s2, s3;
static cudaEvent_t  evR, ev1, ev2, ev3;
static bool s_init = false;

extern "C" void kernel_launch(void* const* d_in, const int* in_sizes, int n_in,
                              void* d_out, int out_size) {
    const float* x  = (const float*)d_in[0];
    const float* rw = (const float*)d_in[1];
    const float* rb = (const float*)d_in[2];
    const float* w1 = (const float*)d_in[3];
    const float* b1 = (const float*)d_in[4];
    const float* w2 = (const float*)d_in[5];
    const float* b2 = (const float*)d_in[6];
    float* out = (float*)d_out;

    if (!s_init) {
        cudaStreamCreateWithFlags(&s1, cudaStreamNonBlocking);
        cudaStreamCreateWithFlags(&s2, cudaStreamNonBlocking);
        cudaStreamCreateWithFlags(&s3, cudaStreamNonBlocking);
        cudaEventCreateWithFlags(&evR, cudaEventDisableTiming);
        cudaEventCreateWithFlags(&ev1, cudaEventDisableTiming);
        cudaEventCreateWithFlags(&ev2, cudaEventDisableTiming);
        cudaEventCreateWithFlags(&ev3, cudaEventDisableTiming);
        cudaFuncSetAttribute(gemm1_kernel, cudaFuncAttributeMaxDynamicSharedMemorySize, SMEM_TOTAL);
        cudaFuncSetAttribute(gemm2_kernel, cudaFuncAttributeMaxDynamicSharedMemorySize, SMEM_TOTAL);
        s_init = true;
    }

    cudaEventRecord(evR, 0);
    cudaStreamWaitEvent(s1, evR, 0);
    cudaStreamWaitEvent(s2, evR, 0);
    cudaStreamWaitEvent(s3, evR, 0);

    cvt_xw1_kernel<<<2048, 256, 0, s1>>>(x, w1);
    cudaEventRecord(ev1, s1);

    zcnt_kernel<<<1, 32, 0, s2>>>();
    router_kernel<<<T_TOKENS / 8, 256, 0, s2>>>(x, rw, rb);
    cudaEventRecord(ev2, s2);

    cvt_w2_kernel<<<2048, 256, 0, s3>>>(w2);
    zero_out_kernel<<<1024, 256, 0, s3>>>(out, out_size / 4);
    cudaEventRecord(ev3, s3);

    cudaStreamWaitEvent(0, ev1, 0);
    cudaStreamWaitEvent(0, ev2, 0);
    gemm1_kernel<<<dim3(MAXTILES, HID / 64), 256, SMEM_TOTAL>>>(b1);

    cudaStreamWaitEvent(0, ev3, 0);
    gemm2_kernel<<<dim3(MAXTILES, DIM / 128), 256, SMEM_TOTAL>>>(b2, out);
}